// round 1
// baseline (speedup 1.0000x reference)
#include <cuda_runtime.h>

#define NT 8192
#define DIM 64
#define THRESH 0.7f
#define NPAD (NT + 64)

// Scratch (static device globals — no allocation)
__device__ float g_V[NT * DIM];          // V = U @ W
__device__ float g_diag[NT];             // sigmoid(v_j . u_j + bias)
__device__ float g_ES[2][NT * DIM];      // gated states (uncompacted, for epilogue)
__device__ float g_Vc[NPAD * DIM];       // compacted V rows (zero padded)
__device__ float g_ESc[2][NPAD * DIM];   // compacted gated states
__device__ int   g_active[NT];
__device__ int   g_count;
__device__ int   g_flag[NT];

__device__ __forceinline__ float sigm(float x) {
    return 1.0f / (1.0f + __expf(-x));
}

// ---------------------------------------------------------------------------
// Kernel A: per-row precompute. grid 64 x 128 threads = 8192 threads (1/row)
// ---------------------------------------------------------------------------
__global__ void precompute_kernel(const float* __restrict__ S,
                                  const float* __restrict__ prof,
                                  const float* __restrict__ U,
                                  const float* __restrict__ W,
                                  const float* __restrict__ bias) {
    __shared__ float Wsm[DIM * DIM];
    int t = threadIdx.x;
    for (int idx = t; idx < DIM * DIM; idx += blockDim.x) Wsm[idx] = W[idx];
    __syncthreads();

    int i = blockIdx.x * blockDim.x + t;

    float u[DIM];
#pragma unroll
    for (int e = 0; e < DIM; e += 4) {
        float4 v4 = *(const float4*)&U[i * DIM + e];
        u[e] = v4.x; u[e + 1] = v4.y; u[e + 2] = v4.z; u[e + 3] = v4.w;
    }

    float dacc = 0.0f;
#pragma unroll 4
    for (int f = 0; f < DIM; f++) {
        float s = 0.0f;
#pragma unroll
        for (int e = 0; e < DIM; e++) s += u[e] * Wsm[e * DIM + f];
        g_V[i * DIM + f] = s;
        dacc += s * u[f];
    }
    g_diag[i] = sigm(dacc + bias[0]);

    float g0 = fmaxf(prof[i] - THRESH, 0.0f);
    float g1 = fmaxf(prof[NT + i] - THRESH, 0.0f);
    g_flag[i] = (g0 > 0.0f || g1 > 0.0f) ? 1 : 0;

#pragma unroll
    for (int d = 0; d < DIM; d += 4) {
        float4 s0 = *(const float4*)&S[i * DIM + d];
        float4 s1 = *(const float4*)&S[(size_t)NT * DIM + i * DIM + d];
        float4 e0 = make_float4(g0 * s0.x, g0 * s0.y, g0 * s0.z, g0 * s0.w);
        float4 e1 = make_float4(g1 * s1.x, g1 * s1.y, g1 * s1.z, g1 * s1.w);
        *(float4*)&g_ES[0][i * DIM + d] = e0;
        *(float4*)&g_ES[1][i * DIM + d] = e1;
    }
}

// ---------------------------------------------------------------------------
// Kernel B: deterministic (order-preserving) compaction scan. 1 CTA.
// ---------------------------------------------------------------------------
__global__ void scan_kernel() {
    __shared__ int sums[256];
    __shared__ int offs[256];
    int t = threadIdx.x;
    const int CH = NT / 256;  // 32
    int base = t * CH;
    int s = 0;
    for (int k = 0; k < CH; k++) s += g_flag[base + k];
    sums[t] = s;
    __syncthreads();
    if (t == 0) {
        int a = 0;
        for (int k = 0; k < 256; k++) { offs[k] = a; a += sums[k]; }
        g_count = a;
    }
    __syncthreads();
    int o = offs[t];
    for (int k = 0; k < CH; k++)
        if (g_flag[base + k]) g_active[o++] = base + k;
}

// ---------------------------------------------------------------------------
// Kernel C: gather compacted rows, zero tail. grid 65 x 128 (8320 threads)
// ---------------------------------------------------------------------------
__global__ void gather_kernel() {
    int k = blockIdx.x * blockDim.x + threadIdx.x;
    if (k >= NPAD) return;
    int cnt = g_count;
    if (k < cnt) {
        int src = g_active[k];
#pragma unroll
        for (int d = 0; d < DIM; d += 4) {
            *(float4*)&g_Vc[k * DIM + d]     = *(const float4*)&g_V[src * DIM + d];
            *(float4*)&g_ESc[0][k * DIM + d] = *(const float4*)&g_ES[0][src * DIM + d];
            *(float4*)&g_ESc[1][k * DIM + d] = *(const float4*)&g_ES[1][src * DIM + d];
        }
    } else {
        float4 z = make_float4(0.f, 0.f, 0.f, 0.f);
#pragma unroll
        for (int d = 0; d < DIM; d += 4) {
            *(float4*)&g_Vc[k * DIM + d]     = z;
            *(float4*)&g_ESc[0][k * DIM + d] = z;
            *(float4*)&g_ESc[1][k * DIM + d] = z;
        }
    }
}

// ---------------------------------------------------------------------------
// Kernel D: fused transfer. grid 128 CTAs (64 j-rows each) x 256 threads.
// smem: uT[64][68] vT[64][68] P[64][64] es[2][64][64]  = 83968 B
// ---------------------------------------------------------------------------
__global__ void __launch_bounds__(256, 1)
main_kernel(const float* __restrict__ U,
            const float* __restrict__ S,
            const float* __restrict__ bias,
            float* __restrict__ out) {
    extern __shared__ float sm[];
    float* uT = sm;                     // 64*68
    float* vT = uT + 64 * 68;           // 64*68
    float* P  = vT + 64 * 68;           // 64*64
    float* es = P + 64 * 64;            // 2*64*64

    const int t  = threadIdx.x;
    const int j0 = blockIdx.x * 64;
    const float bb = bias[0];

    // load uT (k-major, padded stride 68)
    for (int idx = t; idx < 64 * 64; idx += 256) {
        int j = idx >> 6, k = idx & 63;
        uT[k * 68 + j] = U[(j0 + j) * DIM + k];
    }

    float acc[2][16];
#pragma unroll
    for (int b = 0; b < 2; b++)
#pragma unroll
        for (int q = 0; q < 16; q++) acc[b][q] = 0.0f;

    const int cnt = g_count;
    const int nTiles = (cnt + 63) >> 6;
    const int tx = t & 15, ty = t >> 4;
    const int jj = t & 63, d0 = (t >> 6) * 16;

    for (int tile = 0; tile < nTiles; tile++) {
        const int i0 = tile * 64;
        __syncthreads();  // previous-tile consumers done

        for (int idx = t; idx < 64 * 64; idx += 256) {
            int ii = idx >> 6, k = idx & 63;
            vT[k * 68 + ii] = g_Vc[(i0 + ii) * DIM + k];
        }
        for (int idx = t; idx < 64 * 64; idx += 256) {
            es[idx]           = g_ESc[0][i0 * DIM + idx];
            es[4096 + idx]    = g_ESc[1][i0 * DIM + idx];
        }
        __syncthreads();

        // --- score phase: P[i][j] = sigmoid(v_i . u_j + bias), 4x4 micro-tile
        float pa[4][4];
#pragma unroll
        for (int r = 0; r < 4; r++)
#pragma unroll
            for (int c = 0; c < 4; c++) pa[r][c] = 0.0f;

#pragma unroll 4
        for (int k = 0; k < 64; k++) {
            float4 av = *(const float4*)&vT[k * 68 + 4 * ty];
            float4 bu = *(const float4*)&uT[k * 68 + 4 * tx];
            pa[0][0] += av.x * bu.x; pa[0][1] += av.x * bu.y; pa[0][2] += av.x * bu.z; pa[0][3] += av.x * bu.w;
            pa[1][0] += av.y * bu.x; pa[1][1] += av.y * bu.y; pa[1][2] += av.y * bu.z; pa[1][3] += av.y * bu.w;
            pa[2][0] += av.z * bu.x; pa[2][1] += av.z * bu.y; pa[2][2] += av.z * bu.z; pa[2][3] += av.z * bu.w;
            pa[3][0] += av.w * bu.x; pa[3][1] += av.w * bu.y; pa[3][2] += av.w * bu.z; pa[3][3] += av.w * bu.w;
        }
#pragma unroll
        for (int r = 0; r < 4; r++) {
            float4 pv;
            pv.x = sigm(pa[r][0] + bb);
            pv.y = sigm(pa[r][1] + bb);
            pv.z = sigm(pa[r][2] + bb);
            pv.w = sigm(pa[r][3] + bb);
            *(float4*)&P[(4 * ty + r) * 64 + 4 * tx] = pv;
        }
        __syncthreads();

        // --- accumulation phase: acc[b][j][d] += P[i][j] * es[b][i][d]
#pragma unroll 2
        for (int ii = 0; ii < 64; ii++) {
            float p = P[ii * 64 + jj];
#pragma unroll
            for (int b = 0; b < 2; b++) {
                const float* ep = &es[b * 4096 + ii * 64 + d0];
                float4 e0 = *(const float4*)&ep[0];
                float4 e1 = *(const float4*)&ep[4];
                float4 e2 = *(const float4*)&ep[8];
                float4 e3 = *(const float4*)&ep[12];
                acc[b][0]  += p * e0.x; acc[b][1]  += p * e0.y; acc[b][2]  += p * e0.z; acc[b][3]  += p * e0.w;
                acc[b][4]  += p * e1.x; acc[b][5]  += p * e1.y; acc[b][6]  += p * e1.z; acc[b][7]  += p * e1.w;
                acc[b][8]  += p * e2.x; acc[b][9]  += p * e2.y; acc[b][10] += p * e2.z; acc[b][11] += p * e2.w;
                acc[b][12] += p * e3.x; acc[b][13] += p * e3.y; acc[b][14] += p * e3.z; acc[b][15] += p * e3.w;
            }
        }
    }

    // --- epilogue: out = S + acc - diag[j] * ES[b][j]
    const int jg = j0 + jj;
    const float dj = g_diag[jg];
#pragma unroll
    for (int b = 0; b < 2; b++) {
        size_t base = ((size_t)b * NT + jg) * DIM + d0;
#pragma unroll
        for (int q = 0; q < 16; q++) {
            out[base + q] = S[base + q] + acc[b][q] - dj * g_ES[b][jg * DIM + d0 + q];
        }
    }
}

// ---------------------------------------------------------------------------
extern "C" void kernel_launch(void* const* d_in, const int* in_sizes, int n_in,
                              void* d_out, int out_size) {
    const float* S    = (const float*)d_in[0];  // task_states [2,8192,64]
    const float* prof = (const float*)d_in[1];  // proficiency  [2,8192]
    const float* U    = (const float*)d_in[2];  // task_embeddings [8192,64]
    const float* W    = (const float*)d_in[3];  // bilinear_weight [1,64,64]
    const float* bias = (const float*)d_in[4];  // bilinear_bias [1]
    float* out = (float*)d_out;

    static int attr_set = 0;  // not a correctness guard: idempotent attribute
    size_t smem = (size_t)(64 * 68 * 2 + 64 * 64 + 2 * 64 * 64) * sizeof(float);
    cudaFuncSetAttribute(main_kernel, cudaFuncAttributeMaxDynamicSharedMemorySize, (int)smem);
    (void)attr_set;

    precompute_kernel<<<64, 128>>>(S, prof, U, W, bias);
    scan_kernel<<<1, 256>>>();
    gather_kernel<<<65, 128>>>();
    main_kernel<<<128, 256, smem>>>(U, S, bias, out);
}

// round 2
// speedup vs baseline: 1.8575x; 1.8575x over previous
#include <cuda_runtime.h>

#define NT 8192
#define DIM 64
#define THRESH 0.7f
#define NPAD (NT + 64)

// Scratch (static device globals — no allocation)
__device__ float g_V[NT * DIM];          // V = U @ W
__device__ float g_diag[NT];             // sigmoid(v_j . u_j + bias)
__device__ float g_ES[2][NT * DIM];      // gated states (uncompacted, for epilogue)
__device__ float g_Vc[NPAD * DIM];       // compacted V rows (zero padded)
__device__ float g_ESc[2][NPAD * DIM];   // compacted gated states
__device__ int   g_active[NT];
__device__ int   g_count;
__device__ int   g_flag[NT];

__device__ __forceinline__ float sigm(float x) {
    return 1.0f / (1.0f + __expf(-x));
}

// ---------------------------------------------------------------------------
// Kernel A: per-row precompute. grid 64 x 128 threads = 8192 threads (1/row)
// ---------------------------------------------------------------------------
__global__ void precompute_kernel(const float* __restrict__ S,
                                  const float* __restrict__ prof,
                                  const float* __restrict__ U,
                                  const float* __restrict__ W,
                                  const float* __restrict__ bias) {
    __shared__ float Wsm[DIM * DIM];
    int t = threadIdx.x;
    for (int idx = t; idx < DIM * DIM; idx += blockDim.x) Wsm[idx] = W[idx];
    __syncthreads();

    int i = blockIdx.x * blockDim.x + t;

    float u[DIM];
#pragma unroll
    for (int e = 0; e < DIM; e += 4) {
        float4 v4 = *(const float4*)&U[i * DIM + e];
        u[e] = v4.x; u[e + 1] = v4.y; u[e + 2] = v4.z; u[e + 3] = v4.w;
    }

    float dacc = 0.0f;
#pragma unroll 4
    for (int f = 0; f < DIM; f++) {
        float s = 0.0f;
#pragma unroll
        for (int e = 0; e < DIM; e++) s += u[e] * Wsm[e * DIM + f];
        g_V[i * DIM + f] = s;
        dacc += s * u[f];
    }
    g_diag[i] = sigm(dacc + bias[0]);

    float g0 = fmaxf(prof[i] - THRESH, 0.0f);
    float g1 = fmaxf(prof[NT + i] - THRESH, 0.0f);
    g_flag[i] = (g0 > 0.0f || g1 > 0.0f) ? 1 : 0;

#pragma unroll
    for (int d = 0; d < DIM; d += 4) {
        float4 s0 = *(const float4*)&S[i * DIM + d];
        float4 s1 = *(const float4*)&S[(size_t)NT * DIM + i * DIM + d];
        float4 e0 = make_float4(g0 * s0.x, g0 * s0.y, g0 * s0.z, g0 * s0.w);
        float4 e1 = make_float4(g1 * s1.x, g1 * s1.y, g1 * s1.z, g1 * s1.w);
        *(float4*)&g_ES[0][i * DIM + d] = e0;
        *(float4*)&g_ES[1][i * DIM + d] = e1;
    }
}

// ---------------------------------------------------------------------------
// Kernel B: deterministic (order-preserving) compaction scan. 1 CTA.
// ---------------------------------------------------------------------------
__global__ void scan_kernel() {
    __shared__ int sums[256];
    __shared__ int offs[256];
    int t = threadIdx.x;
    const int CH = NT / 256;  // 32
    int base = t * CH;
    int s = 0;
    for (int k = 0; k < CH; k++) s += g_flag[base + k];
    sums[t] = s;
    __syncthreads();
    if (t == 0) {
        int a = 0;
        for (int k = 0; k < 256; k++) { offs[k] = a; a += sums[k]; }
        g_count = a;
    }
    __syncthreads();
    int o = offs[t];
    for (int k = 0; k < CH; k++)
        if (g_flag[base + k]) g_active[o++] = base + k;
}

// ---------------------------------------------------------------------------
// Kernel C: gather compacted rows, zero tail. grid 65 x 128 (8320 threads)
// ---------------------------------------------------------------------------
__global__ void gather_kernel() {
    int k = blockIdx.x * blockDim.x + threadIdx.x;
    if (k >= NPAD) return;
    int cnt = g_count;
    if (k < cnt) {
        int src = g_active[k];
#pragma unroll
        for (int d = 0; d < DIM; d += 4) {
            *(float4*)&g_Vc[k * DIM + d]     = *(const float4*)&g_V[src * DIM + d];
            *(float4*)&g_ESc[0][k * DIM + d] = *(const float4*)&g_ES[0][src * DIM + d];
            *(float4*)&g_ESc[1][k * DIM + d] = *(const float4*)&g_ES[1][src * DIM + d];
        }
    } else {
        float4 z = make_float4(0.f, 0.f, 0.f, 0.f);
#pragma unroll
        for (int d = 0; d < DIM; d += 4) {
            *(float4*)&g_Vc[k * DIM + d]     = z;
            *(float4*)&g_ESc[0][k * DIM + d] = z;
            *(float4*)&g_ESc[1][k * DIM + d] = z;
        }
    }
}

// ---------------------------------------------------------------------------
// Kernel D: fused transfer. grid 128 CTAs (64 j-rows each) x 256 threads.
// Both phases are 4x4-register-tiled GEMM fragments:
//   score: P[i][j]   = sigm(sum_k vT[k][i]*uT[k][j] + b)
//   accum: acc[j][d] += sum_i P[i][j]*es[b][i][d]   (P float4 shared across b)
// smem: uT[64][68] vT[64][68] P[64][64] es[2][64][64] = 83968 B
// ---------------------------------------------------------------------------
__global__ void __launch_bounds__(256, 1)
main_kernel(const float* __restrict__ U,
            const float* __restrict__ S,
            const float* __restrict__ bias,
            float* __restrict__ out) {
    extern __shared__ float sm[];
    float* uT = sm;                     // 64*68
    float* vT = uT + 64 * 68;           // 64*68
    float* P  = vT + 64 * 68;           // 64*64
    float* es = P + 64 * 64;            // 2*64*64

    const int t  = threadIdx.x;
    const int j0 = blockIdx.x * 64;
    const float bb = bias[0];
    const int tx = t & 15, ty = t >> 4;

    // load uT (k-major, padded stride 68)
    for (int idx = t; idx < 64 * 64; idx += 256) {
        int j = idx >> 6, k = idx & 63;
        uT[k * 68 + j] = U[(j0 + j) * DIM + k];
    }

    // accumulators: acc[b][jr][dc] for j = 4*ty + jr, d = 4*tx + dc
    float acc[2][4][4];
#pragma unroll
    for (int b = 0; b < 2; b++)
#pragma unroll
        for (int r = 0; r < 4; r++)
#pragma unroll
            for (int c = 0; c < 4; c++) acc[b][r][c] = 0.0f;

    const int cnt = g_count;
    const int nTiles = (cnt + 63) >> 6;

    for (int tile = 0; tile < nTiles; tile++) {
        const int i0 = tile * 64;
        __syncthreads();  // previous-tile consumers done

        for (int idx = t; idx < 64 * 64; idx += 256) {
            int ii = idx >> 6, k = idx & 63;
            vT[k * 68 + ii] = g_Vc[(i0 + ii) * DIM + k];
        }
        for (int idx = t; idx < 64 * 64; idx += 256) {
            es[idx]        = g_ESc[0][i0 * DIM + idx];
            es[4096 + idx] = g_ESc[1][i0 * DIM + idx];
        }
        __syncthreads();

        // --- score phase: P[4ty+r][4tx+c], 4x4 micro-tile
        float pa[4][4];
#pragma unroll
        for (int r = 0; r < 4; r++)
#pragma unroll
            for (int c = 0; c < 4; c++) pa[r][c] = 0.0f;

#pragma unroll 4
        for (int k = 0; k < 64; k++) {
            float4 av = *(const float4*)&vT[k * 68 + 4 * ty];  // i rows
            float4 bu = *(const float4*)&uT[k * 68 + 4 * tx];  // j cols
            pa[0][0] += av.x * bu.x; pa[0][1] += av.x * bu.y; pa[0][2] += av.x * bu.z; pa[0][3] += av.x * bu.w;
            pa[1][0] += av.y * bu.x; pa[1][1] += av.y * bu.y; pa[1][2] += av.y * bu.z; pa[1][3] += av.y * bu.w;
            pa[2][0] += av.z * bu.x; pa[2][1] += av.z * bu.y; pa[2][2] += av.z * bu.z; pa[2][3] += av.z * bu.w;
            pa[3][0] += av.w * bu.x; pa[3][1] += av.w * bu.y; pa[3][2] += av.w * bu.z; pa[3][3] += av.w * bu.w;
        }
#pragma unroll
        for (int r = 0; r < 4; r++) {
            float4 pv;
            pv.x = sigm(pa[r][0] + bb);
            pv.y = sigm(pa[r][1] + bb);
            pv.z = sigm(pa[r][2] + bb);
            pv.w = sigm(pa[r][3] + bb);
            *(float4*)&P[(4 * ty + r) * 64 + 4 * tx] = pv;
        }
        __syncthreads();

        // --- accumulation: register-tiled outer product over i (= k here)
        //     3 LDS.128 -> 32 FMA per k
#pragma unroll 4
        for (int k = 0; k < 64; k++) {
            float4 pj = *(const float4*)&P[k * 64 + 4 * ty];          // 4 j's (broadcast-heavy)
            float4 e0 = *(const float4*)&es[k * 64 + 4 * tx];         // b=0, 4 d's
            float4 e1 = *(const float4*)&es[4096 + k * 64 + 4 * tx];  // b=1, 4 d's
            acc[0][0][0] += pj.x * e0.x; acc[0][0][1] += pj.x * e0.y; acc[0][0][2] += pj.x * e0.z; acc[0][0][3] += pj.x * e0.w;
            acc[0][1][0] += pj.y * e0.x; acc[0][1][1] += pj.y * e0.y; acc[0][1][2] += pj.y * e0.z; acc[0][1][3] += pj.y * e0.w;
            acc[0][2][0] += pj.z * e0.x; acc[0][2][1] += pj.z * e0.y; acc[0][2][2] += pj.z * e0.z; acc[0][2][3] += pj.z * e0.w;
            acc[0][3][0] += pj.w * e0.x; acc[0][3][1] += pj.w * e0.y; acc[0][3][2] += pj.w * e0.z; acc[0][3][3] += pj.w * e0.w;
            acc[1][0][0] += pj.x * e1.x; acc[1][0][1] += pj.x * e1.y; acc[1][0][2] += pj.x * e1.z; acc[1][0][3] += pj.x * e1.w;
            acc[1][1][0] += pj.y * e1.x; acc[1][1][1] += pj.y * e1.y; acc[1][1][2] += pj.y * e1.z; acc[1][1][3] += pj.y * e1.w;
            acc[1][2][0] += pj.z * e1.x; acc[1][2][1] += pj.z * e1.y; acc[1][2][2] += pj.z * e1.z; acc[1][2][3] += pj.z * e1.w;
            acc[1][3][0] += pj.w * e1.x; acc[1][3][1] += pj.w * e1.y; acc[1][3][2] += pj.w * e1.z; acc[1][3][3] += pj.w * e1.w;
        }
    }

    // --- epilogue: out = S + acc - diag[j] * ES[b][j]  (per-thread 2x4x4 tile)
#pragma unroll
    for (int r = 0; r < 4; r++) {
        const int jg = j0 + 4 * ty + r;
        const float dj = g_diag[jg];
        const int d0 = 4 * tx;
#pragma unroll
        for (int b = 0; b < 2; b++) {
            size_t base = ((size_t)b * NT + jg) * DIM + d0;
            float4 s4 = *(const float4*)&S[base];
            float4 e4 = *(const float4*)&g_ES[b][jg * DIM + d0];
            float4 o4;
            o4.x = s4.x + acc[b][r][0] - dj * e4.x;
            o4.y = s4.y + acc[b][r][1] - dj * e4.y;
            o4.z = s4.z + acc[b][r][2] - dj * e4.z;
            o4.w = s4.w + acc[b][r][3] - dj * e4.w;
            *(float4*)&out[base] = o4;
        }
    }
}

// ---------------------------------------------------------------------------
extern "C" void kernel_launch(void* const* d_in, const int* in_sizes, int n_in,
                              void* d_out, int out_size) {
    const float* S    = (const float*)d_in[0];  // task_states [2,8192,64]
    const float* prof = (const float*)d_in[1];  // proficiency  [2,8192]
    const float* U    = (const float*)d_in[2];  // task_embeddings [8192,64]
    const float* W    = (const float*)d_in[3];  // bilinear_weight [1,64,64]
    const float* bias = (const float*)d_in[4];  // bilinear_bias [1]
    float* out = (float*)d_out;

    size_t smem = (size_t)(64 * 68 * 2 + 64 * 64 + 2 * 64 * 64) * sizeof(float);
    cudaFuncSetAttribute(main_kernel, cudaFuncAttributeMaxDynamicSharedMemorySize, (int)smem);

    precompute_kernel<<<64, 128>>>(S, prof, U, W, bias);
    scan_kernel<<<1, 256>>>();
    gather_kernel<<<65, 128>>>();
    main_kernel<<<128, 256, smem>>>(U, S, bias, out);
}

// round 4
// speedup vs baseline: 8.0139x; 4.3143x over previous
#include <cuda_runtime.h>
#include <cuda_fp16.h>
#include <cstdint>

#define NT 8192
#define DIM 64
#define THRESH 0.7f
#define NPAD 8320          // 65 * 128
#define SPLIT 4

// ---------------- global scratch (static, no allocation) ----------------
__device__ float g_V[NT * DIM];
__device__ float g_diag[NT];
__device__ float g_ES[2][NT * DIM];
__device__ __half g_Uh[NT * DIM], g_Ul[NT * DIM];      // U split hi/lo
__device__ __half g_Vh[NPAD * DIM], g_Vl[NPAD * DIM];  // compacted V split hi/lo
__device__ __half g_E[128 * NPAD];                     // ES^T: rows bd=(b*64+d), cols i
__device__ float g_part[SPLIT][NT * 128];
__device__ int g_active[NT];
__device__ int g_count;
__device__ int g_flag[NT];

// ---------------- helpers ----------------
__device__ __forceinline__ uint32_t smem_u32(const void* p) {
    uint32_t a;
    asm("{ .reg .u64 t; cvta.to.shared.u64 t, %1; cvt.u32.u64 %0, t; }" : "=r"(a) : "l"(p));
    return a;
}
#define CP16(d, s) asm volatile("cp.async.cg.shared.global [%0], [%1], 16;" :: "r"(d), "l"(s) : "memory")
#define CP_COMMIT() asm volatile("cp.async.commit_group;" ::: "memory")
#define CP_WAIT(n) asm volatile("cp.async.wait_group %0;" :: "n"(n) : "memory")

#define MMA16816(c, a, b0, b1) \
    asm volatile("mma.sync.aligned.m16n8k16.row.col.f32.f16.f16.f32 " \
                 "{%0,%1,%2,%3}, {%4,%5,%6,%7}, {%8,%9}, {%0,%1,%2,%3};" \
                 : "+f"((c)[0]), "+f"((c)[1]), "+f"((c)[2]), "+f"((c)[3]) \
                 : "r"((a)[0]), "r"((a)[1]), "r"((a)[2]), "r"((a)[3]), \
                   "r"(b0), "r"(b1))

__device__ __forceinline__ float sigm(float x) { return 1.0f / (1.0f + __expf(-x)); }
__device__ __forceinline__ float sigmf(float x) {
    return __fdividef(1.0f, 1.0f + __expf(-x));
}
__device__ __forceinline__ uint32_t packh2(float x, float y) {
    __half2 h = __floats2half2_rn(x, y);
    return *(uint32_t*)&h;
}

// ---------------------------------------------------------------------------
// Kernel A: per-row precompute + fp16 split of U. 64 x 128.
// ---------------------------------------------------------------------------
__global__ void precompute_kernel(const float* __restrict__ S,
                                  const float* __restrict__ prof,
                                  const float* __restrict__ U,
                                  const float* __restrict__ W,
                                  const float* __restrict__ bias) {
    __shared__ float Wsm[DIM * DIM];
    int t = threadIdx.x;
    for (int idx = t; idx < DIM * DIM; idx += blockDim.x) Wsm[idx] = W[idx];
    __syncthreads();

    int i = blockIdx.x * blockDim.x + t;

    float u[DIM];
#pragma unroll
    for (int e = 0; e < DIM; e += 4) {
        float4 v4 = *(const float4*)&U[i * DIM + e];
        u[e] = v4.x; u[e + 1] = v4.y; u[e + 2] = v4.z; u[e + 3] = v4.w;
    }

    float dacc = 0.0f;
#pragma unroll 4
    for (int f = 0; f < DIM; f++) {
        float s = 0.0f;
#pragma unroll
        for (int e = 0; e < DIM; e++) s += u[e] * Wsm[e * DIM + f];
        g_V[i * DIM + f] = s;
        dacc += s * u[f];
    }
    g_diag[i] = sigm(dacc + bias[0]);

    // split U into fp16 hi/lo
#pragma unroll
    for (int d = 0; d < DIM; d += 2) {
        __half h0 = __float2half_rn(u[d]);
        __half h1 = __float2half_rn(u[d + 1]);
        __half l0 = __float2half_rn(u[d] - __half2float(h0));
        __half l1 = __float2half_rn(u[d + 1] - __half2float(h1));
        __half2 ph = __halves2half2(h0, h1);
        __half2 pl = __halves2half2(l0, l1);
        *(__half2*)&g_Uh[i * DIM + d] = ph;
        *(__half2*)&g_Ul[i * DIM + d] = pl;
    }

    float g0 = fmaxf(prof[i] - THRESH, 0.0f);
    float g1 = fmaxf(prof[NT + i] - THRESH, 0.0f);
    g_flag[i] = (g0 > 0.0f || g1 > 0.0f) ? 1 : 0;

#pragma unroll
    for (int d = 0; d < DIM; d += 4) {
        float4 s0 = *(const float4*)&S[i * DIM + d];
        float4 s1 = *(const float4*)&S[(size_t)NT * DIM + i * DIM + d];
        float4 e0 = make_float4(g0 * s0.x, g0 * s0.y, g0 * s0.z, g0 * s0.w);
        float4 e1 = make_float4(g1 * s1.x, g1 * s1.y, g1 * s1.z, g1 * s1.w);
        *(float4*)&g_ES[0][i * DIM + d] = e0;
        *(float4*)&g_ES[1][i * DIM + d] = e1;
    }
}

// ---------------------------------------------------------------------------
// Kernel B: deterministic compaction scan. 1 CTA.
// ---------------------------------------------------------------------------
__global__ void scan_kernel() {
    __shared__ int sums[256];
    __shared__ int offs[256];
    int t = threadIdx.x;
    const int CH = NT / 256;
    int base = t * CH;
    int s = 0;
    for (int k = 0; k < CH; k++) s += g_flag[base + k];
    sums[t] = s;
    __syncthreads();
    if (t == 0) {
        int a = 0;
        for (int k = 0; k < 256; k++) { offs[k] = a; a += sums[k]; }
        g_count = a;
    }
    __syncthreads();
    int o = offs[t];
    for (int k = 0; k < CH; k++)
        if (g_flag[base + k]) g_active[o++] = base + k;
}

// ---------------------------------------------------------------------------
// Kernel C1: gather compacted V rows -> fp16 hi/lo, zero pad. 65 x 128.
// ---------------------------------------------------------------------------
__global__ void gatherV_kernel() {
    int k = blockIdx.x * 128 + threadIdx.x;
    if (k >= NPAD) return;
    int cnt = g_count;
    if (k < cnt) {
        int src = g_active[k];
#pragma unroll
        for (int d = 0; d < DIM; d += 2) {
            float v0 = g_V[src * DIM + d];
            float v1 = g_V[src * DIM + d + 1];
            __half h0 = __float2half_rn(v0);
            __half h1 = __float2half_rn(v1);
            __half l0 = __float2half_rn(v0 - __half2float(h0));
            __half l1 = __float2half_rn(v1 - __half2float(h1));
            *(__half2*)&g_Vh[k * DIM + d] = __halves2half2(h0, h1);
            *(__half2*)&g_Vl[k * DIM + d] = __halves2half2(l0, l1);
        }
    } else {
        uint4 z = make_uint4(0, 0, 0, 0);
#pragma unroll
        for (int d = 0; d < DIM; d += 8) {
            *(uint4*)&g_Vh[k * DIM + d] = z;
            *(uint4*)&g_Vl[k * DIM + d] = z;
        }
    }
}

// ---------------------------------------------------------------------------
// Kernel C2: gather + transpose ES -> ES^T fp16 [128 bd][NPAD i]. 65 x 256.
// ---------------------------------------------------------------------------
__global__ void gatherE_kernel() {
    extern __shared__ __half sh[];  // [128 k][130 bd]
    int c = blockIdx.x, t = threadIdx.x;
    int cnt = g_count;
    for (int idx = t; idx < 128 * 128; idx += 256) {
        int k = idx >> 7, bd = idx & 127;
        int gi = c * 128 + k;
        float v = 0.0f;
        if (gi < cnt) {
            int src = g_active[gi];
            v = g_ES[bd >> 6][src * DIM + (bd & 63)];
        }
        sh[k * 130 + bd] = __float2half_rn(v);
    }
    __syncthreads();
    int r = t >> 1, hh = t & 1;
    int ibase = c * 128 + hh * 64;
#pragma unroll 8
    for (int kk = 0; kk < 64; kk += 2) {
        int k0 = hh * 64 + kk;
        __half2 p = __halves2half2(sh[k0 * 130 + r], sh[(k0 + 1) * 130 + r]);
        *(__half2*)&g_E[r * NPAD + ibase + kk] = p;
    }
}

// ---------------------------------------------------------------------------
// Main HMMA kernel. grid (64 j-tiles, SPLIT) x 256 threads (8 warps).
// Each warp: 16 j rows. GEMM1: scores[16j x 128i] (fp16 3-pass, fp32 acc).
// P = sigmoid stays in registers, re-packed as A fragments for GEMM2:
// leaked[16j x 128bd] accumulated across i-tiles in fp32 registers.
// SMEM layout (bytes):
//   U_h [128][72]h : 0      (18432)
//   U_l [128][72]h : 18432
//   V stage s      : 36864 + s*36864  {vh:+0, vl:+18432}
//   E stage s      : 110592 + s*34816   ([128][136]h)
// total 180224
// ---------------------------------------------------------------------------
#define SM_UL  18432
#define SM_V(s)  (36864 + (s) * 36864)
#define SM_E(s)  (110592 + (s) * 34816)
#define SMEM_MAIN 180224

__device__ __forceinline__ void prefetch_tile(char* sm, uint32_t sb, int s, int i0, int t) {
    uint32_t vh = sb + SM_V(s), vl = vh + SM_UL, eb = sb + SM_E(s);
    // V hi/lo: 128 rows x 8 chunks of 16B, dst stride 144B
#pragma unroll
    for (int it = 0; it < 4; it++) {
        int idx = it * 256 + t;
        int row = idx >> 3, ch = idx & 7;
        uint32_t doff = (uint32_t)(row * 144 + ch * 16);
        CP16(vh + doff, (const char*)&g_Vh[(i0 + row) * DIM + ch * 8]);
        CP16(vl + doff, (const char*)&g_Vl[(i0 + row) * DIM + ch * 8]);
    }
    // E: 128 rows x 16 chunks of 16B, dst stride 272B
#pragma unroll
    for (int it = 0; it < 8; it++) {
        int idx = it * 256 + t;
        int row = idx >> 4, ch = idx & 15;
        CP16(eb + (uint32_t)(row * 272 + ch * 16),
             (const char*)&g_E[row * NPAD + i0 + ch * 8]);
    }
}

__global__ void __launch_bounds__(256, 1)
main_mma(const float* __restrict__ bias) {
    extern __shared__ char sm[];
    const uint32_t sb = smem_u32(sm);
    const int t = threadIdx.x;
    const int w = t >> 5, lane = t & 31;
    const int gid = lane >> 2, tig = lane & 3;
    const int jt = blockIdx.x, part = blockIdx.y;
    const int j0 = jt * 128;
    const float bb = bias[0];

    __half* u_h = (__half*)sm;
    __half* u_l = (__half*)(sm + SM_UL);

    const int cnt = g_count;
    const int nT = (cnt + 127) >> 7;
    const int t0 = (part * nT) / SPLIT;
    const int t1 = ((part + 1) * nT) / SPLIT;
    const int Tl = t1 - t0;

    // stage U tile (persistent): 128 rows x 8 chunks x {h,l}
#pragma unroll
    for (int it = 0; it < 4; it++) {
        int idx = it * 256 + t;
        int row = idx >> 3, ch = idx & 7;
        *(uint4*)(u_h + row * 72 + ch * 8) = *(const uint4*)&g_Uh[(j0 + row) * DIM + ch * 8];
        *(uint4*)(u_l + row * 72 + ch * 8) = *(const uint4*)&g_Ul[(j0 + row) * DIM + ch * 8];
    }

    float acc2[16][4];
#pragma unroll
    for (int nt = 0; nt < 16; nt++)
#pragma unroll
        for (int q = 0; q < 4; q++) acc2[nt][q] = 0.0f;

    if (Tl > 0) {
        prefetch_tile(sm, sb, 0, t0 * 128, t);
        CP_COMMIT();
    }
    __syncthreads();  // U visible (and stage-0 committed)

    // persistent A fragments of U (hi and lo) for the 4 k-chunks
    uint32_t au[4][4], al[4][4];
    {
        const __half* ubase_h = u_h + (16 * w + gid) * 72 + 2 * tig;
        const __half* ubase_l = u_l + (16 * w + gid) * 72 + 2 * tig;
#pragma unroll
        for (int kk = 0; kk < 4; kk++) {
            const __half* ph = ubase_h + 16 * kk;
            const __half* pl = ubase_l + 16 * kk;
            au[kk][0] = *(const uint32_t*)ph;
            au[kk][1] = *(const uint32_t*)(ph + 8 * 72);
            au[kk][2] = *(const uint32_t*)(ph + 8);
            au[kk][3] = *(const uint32_t*)(ph + 8 * 72 + 8);
            al[kk][0] = *(const uint32_t*)pl;
            al[kk][1] = *(const uint32_t*)(pl + 8 * 72);
            al[kk][2] = *(const uint32_t*)(pl + 8);
            al[kk][3] = *(const uint32_t*)(pl + 8 * 72 + 8);
        }
    }

    for (int lt = 0; lt < Tl; lt++) {
        const int s = lt & 1;
        if (lt + 1 < Tl) {
            prefetch_tile(sm, sb, s ^ 1, (t0 + lt + 1) * 128, t);
            CP_COMMIT();
            CP_WAIT(1);
        } else {
            CP_WAIT(0);
        }
        __syncthreads();  // current stage visible to all threads

        const __half* vh = (const __half*)(sm + SM_V(s));
        const __half* vl = vh + SM_UL / 2;
        const __half* eb = (const __half*)(sm + SM_E(s));

        // GEMM1 + sigmoid + pack, fused per q (pair of n8 tiles)
        uint32_t ra[8][4];
#pragma unroll
        for (int q = 0; q < 8; q++) {
            float pa[2][4];
#pragma unroll
            for (int ss = 0; ss < 2; ss++) {
                pa[ss][0] = pa[ss][1] = pa[ss][2] = pa[ss][3] = 0.0f;
                const int nt = 2 * q + ss;
                const __half* vrow_h = vh + (8 * nt + gid) * 72 + 2 * tig;
                const __half* vrow_l = vl + (8 * nt + gid) * 72 + 2 * tig;
#pragma unroll
                for (int kk = 0; kk < 4; kk++) {
                    uint32_t bh0 = *(const uint32_t*)(vrow_h + 16 * kk);
                    uint32_t bh1 = *(const uint32_t*)(vrow_h + 16 * kk + 8);
                    uint32_t bl0 = *(const uint32_t*)(vrow_l + 16 * kk);
                    uint32_t bl1 = *(const uint32_t*)(vrow_l + 16 * kk + 8);
                    MMA16816(pa[ss], au[kk], bh0, bh1);
                    MMA16816(pa[ss], al[kk], bh0, bh1);
                    MMA16816(pa[ss], au[kk], bl0, bl1);
                }
            }
            ra[q][0] = packh2(sigmf(pa[0][0] + bb), sigmf(pa[0][1] + bb));
            ra[q][1] = packh2(sigmf(pa[0][2] + bb), sigmf(pa[0][3] + bb));
            ra[q][2] = packh2(sigmf(pa[1][0] + bb), sigmf(pa[1][1] + bb));
            ra[q][3] = packh2(sigmf(pa[1][2] + bb), sigmf(pa[1][3] + bb));
        }

        // GEMM2: leaked[16j x 128bd] += P[16j x 128i] * E^T[128i x 128bd]
#pragma unroll
        for (int nt = 0; nt < 16; nt++) {
            const __half* erow = eb + (8 * nt + gid) * 136 + 2 * tig;
#pragma unroll
            for (int q = 0; q < 8; q++) {
                uint32_t b0 = *(const uint32_t*)(erow + 16 * q);
                uint32_t b1 = *(const uint32_t*)(erow + 16 * q + 8);
                MMA16816(acc2[nt], ra[q], b0, b1);
            }
        }
        __syncthreads();  // done reading stage s; safe to overwrite next iter
    }

    // write partial leaked
    {
        const int j = j0 + 16 * w + gid;
        float* dst0 = &g_part[part][(size_t)j * 128];
        float* dst1 = &g_part[part][(size_t)(j + 8) * 128];
#pragma unroll
        for (int nt = 0; nt < 16; nt++) {
            const int bd = 8 * nt + 2 * tig;
            *(float2*)(dst0 + bd) = make_float2(acc2[nt][0], acc2[nt][1]);
            *(float2*)(dst1 + bd) = make_float2(acc2[nt][2], acc2[nt][3]);
        }
    }
}

// ---------------------------------------------------------------------------
// Combine: out = S + sum(parts) - diag * ES. grid 1024 x 256 (float4).
// ---------------------------------------------------------------------------
__global__ void combine_kernel(const float* __restrict__ S, float* __restrict__ out) {
    int f = blockIdx.x * blockDim.x + threadIdx.x;
    int e = f * 4;
    int b = e >> 19;
    int r = (e >> 6) & (NT - 1);
    int d = e & 63;
    float4 s4 = *(const float4*)&S[e];
    float4 a0 = *(const float4*)&g_part[0][(size_t)r * 128 + b * 64 + d];
    float4 a1 = *(const float4*)&g_part[1][(size_t)r * 128 + b * 64 + d];
    float4 a2 = *(const float4*)&g_part[2][(size_t)r * 128 + b * 64 + d];
    float4 a3 = *(const float4*)&g_part[3][(size_t)r * 128 + b * 64 + d];
    float dj = g_diag[r];
    float4 e4 = *(const float4*)&g_ES[b][r * DIM + d];
    float4 o;
    o.x = s4.x + ((a0.x + a1.x) + (a2.x + a3.x)) - dj * e4.x;
    o.y = s4.y + ((a0.y + a1.y) + (a2.y + a3.y)) - dj * e4.y;
    o.z = s4.z + ((a0.z + a1.z) + (a2.z + a3.z)) - dj * e4.z;
    o.w = s4.w + ((a0.w + a1.w) + (a2.w + a3.w)) - dj * e4.w;
    *(float4*)&out[e] = o;
}

// ---------------------------------------------------------------------------
extern "C" void kernel_launch(void* const* d_in, const int* in_sizes, int n_in,
                              void* d_out, int out_size) {
    const float* S    = (const float*)d_in[0];
    const float* prof = (const float*)d_in[1];
    const float* U    = (const float*)d_in[2];
    const float* W    = (const float*)d_in[3];
    const float* bias = (const float*)d_in[4];
    float* out = (float*)d_out;

    cudaFuncSetAttribute(main_mma, cudaFuncAttributeMaxDynamicSharedMemorySize, SMEM_MAIN);
    cudaFuncSetAttribute(gatherE_kernel, cudaFuncAttributeMaxDynamicSharedMemorySize,
                         128 * 130 * (int)sizeof(__half));

    precompute_kernel<<<64, 128>>>(S, prof, U, W, bias);
    scan_kernel<<<1, 256>>>();
    gatherV_kernel<<<65, 128>>>();
    gatherE_kernel<<<65, 256, 128 * 130 * sizeof(__half)>>>();
    main_mma<<<dim3(64, SPLIT), 256, SMEM_MAIN>>>(bias);
    combine_kernel<<<1024, 256>>>(S, out);
}

// round 7
// speedup vs baseline: 8.9533x; 1.1172x over previous
#include <cuda_runtime.h>
#include <cuda_fp16.h>
#include <cstdint>

#define NT 8192
#define DIM 64
#define THRESH 0.7f
#define NPAD 8320          // 65 * 128
#define SPLIT 2

// ---------------- global scratch (static, no allocation) ----------------
__device__ float g_V[NT * DIM];
__device__ float g_diag[NT];
__device__ float g_ES[2][NT * DIM];
__device__ __half g_Uh[NT * DIM], g_Ul[NT * DIM];      // U split hi/lo
__device__ __half g_Vh[NPAD * DIM], g_Vl[NPAD * DIM];  // compacted V split hi/lo
__device__ __half g_E[128 * NPAD];                     // ES^T: rows bd=(b*64+d), cols i
__device__ float g_part[SPLIT][NT * 128];
__device__ int g_active[NT];
__device__ int g_count;
__device__ int g_flag[NT];

// ---------------- helpers ----------------
__device__ __forceinline__ uint32_t smem_u32(const void* p) {
    uint32_t a;
    asm("{ .reg .u64 t; cvta.to.shared.u64 t, %1; cvt.u32.u64 %0, t; }" : "=r"(a) : "l"(p));
    return a;
}
#define CP16(d, s) asm volatile("cp.async.cg.shared.global [%0], [%1], 16;" :: "r"(d), "l"(s) : "memory")
#define CP_COMMIT() asm volatile("cp.async.commit_group;" ::: "memory")
#define CP_WAIT(n) asm volatile("cp.async.wait_group %0;" :: "n"(n) : "memory")

#define MMA16816(c, a, b0, b1) \
    asm volatile("mma.sync.aligned.m16n8k16.row.col.f32.f16.f16.f32 " \
                 "{%0,%1,%2,%3}, {%4,%5,%6,%7}, {%8,%9}, {%0,%1,%2,%3};" \
                 : "+f"((c)[0]), "+f"((c)[1]), "+f"((c)[2]), "+f"((c)[3]) \
                 : "r"((a)[0]), "r"((a)[1]), "r"((a)[2]), "r"((a)[3]), \
                   "r"(b0), "r"(b1))

__device__ __forceinline__ float sigm(float x) { return 1.0f / (1.0f + __expf(-x)); }
__device__ __forceinline__ float sigmf(float x) {
    return __fdividef(1.0f, 1.0f + __expf(-x));
}
__device__ __forceinline__ uint32_t packh2(float x, float y) {
    __half2 h = __floats2half2_rn(x, y);
    return *(uint32_t*)&h;
}

// ---------------------------------------------------------------------------
// Kernel A: per-row precompute + fp16 split of U. grid 64 x 256 (2 thr/row).
// ---------------------------------------------------------------------------
__global__ void precompute_kernel(const float* __restrict__ S,
                                  const float* __restrict__ prof,
                                  const float* __restrict__ U,
                                  const float* __restrict__ W,
                                  const float* __restrict__ bias) {
    __shared__ float Wsm[DIM * DIM];
    int t = threadIdx.x;
    for (int idx = t; idx < DIM * DIM; idx += blockDim.x) Wsm[idx] = W[idx];
    __syncthreads();

    const int half = t & 1;
    const int i = blockIdx.x * 128 + (t >> 1);

    float u[DIM];
#pragma unroll
    for (int e = 0; e < DIM; e += 4) {
        float4 v4 = *(const float4*)&U[i * DIM + e];
        u[e] = v4.x; u[e + 1] = v4.y; u[e + 2] = v4.z; u[e + 3] = v4.w;
    }

    // each thread computes 32 f-columns of V and a partial diag dot
    float dacc = 0.0f;
    const int f0 = half * 32;
#pragma unroll 4
    for (int fo = 0; fo < 32; fo++) {
        int f = f0 + fo;
        float s = 0.0f;
#pragma unroll
        for (int e = 0; e < DIM; e++) s += u[e] * Wsm[e * DIM + f];
        g_V[i * DIM + f] = s;
        dacc += s * u[f];
    }
    dacc += __shfl_xor_sync(0xffffffffu, dacc, 1);
    if (half == 0) g_diag[i] = sigm(dacc + bias[0]);

    // split U into fp16 hi/lo (each thread: its 32-d half)
#pragma unroll
    for (int d = f0; d < f0 + 32; d += 2) {
        __half h0 = __float2half_rn(u[d]);
        __half h1 = __float2half_rn(u[d + 1]);
        __half l0 = __float2half_rn(u[d] - __half2float(h0));
        __half l1 = __float2half_rn(u[d + 1] - __half2float(h1));
        *(__half2*)&g_Uh[i * DIM + d] = __halves2half2(h0, h1);
        *(__half2*)&g_Ul[i * DIM + d] = __halves2half2(l0, l1);
    }

    // gating: thread handles batch = half
    float gg = fmaxf(prof[half * NT + i] - THRESH, 0.0f);
    float go = __shfl_xor_sync(0xffffffffu, gg, 1);
    if (half == 0) g_flag[i] = (gg > 0.0f || go > 0.0f) ? 1 : 0;

#pragma unroll
    for (int d = 0; d < DIM; d += 4) {
        size_t src = (size_t)half * NT * DIM + i * DIM + d;
        float4 s4 = *(const float4*)&S[src];
        float4 e4 = make_float4(gg * s4.x, gg * s4.y, gg * s4.z, gg * s4.w);
        *(float4*)&g_ES[half][i * DIM + d] = e4;
    }
}

// ---------------------------------------------------------------------------
// Kernel B: deterministic compaction scan (Hillis-Steele). 1 CTA x 256.
// ---------------------------------------------------------------------------
__global__ void scan_kernel() {
    __shared__ int sums[256];
    int t = threadIdx.x;
    const int CH = NT / 256;  // 32
    int base = t * CH;
    int flags[CH];
    int s = 0;
#pragma unroll
    for (int k = 0; k < CH; k++) { flags[k] = g_flag[base + k]; s += flags[k]; }
    sums[t] = s;
    __syncthreads();
#pragma unroll
    for (int off = 1; off < 256; off <<= 1) {
        int v = (t >= off) ? sums[t - off] : 0;
        __syncthreads();
        sums[t] += v;
        __syncthreads();
    }
    if (t == 255) g_count = sums[255];
    int o = sums[t] - s;  // exclusive prefix
#pragma unroll
    for (int k = 0; k < CH; k++)
        if (flags[k]) g_active[o++] = base + k;
}

// ---------------------------------------------------------------------------
// Kernel C1: gather compacted V rows -> fp16 hi/lo, zero pad. 65 x 128.
// ---------------------------------------------------------------------------
__global__ void gatherV_kernel() {
    int k = blockIdx.x * 128 + threadIdx.x;
    if (k >= NPAD) return;
    int cnt = g_count;
    if (k < cnt) {
        int src = g_active[k];
#pragma unroll
        for (int d = 0; d < DIM; d += 2) {
            float v0 = g_V[src * DIM + d];
            float v1 = g_V[src * DIM + d + 1];
            __half h0 = __float2half_rn(v0);
            __half h1 = __float2half_rn(v1);
            __half l0 = __float2half_rn(v0 - __half2float(h0));
            __half l1 = __float2half_rn(v1 - __half2float(h1));
            *(__half2*)&g_Vh[k * DIM + d] = __halves2half2(h0, h1);
            *(__half2*)&g_Vl[k * DIM + d] = __halves2half2(l0, l1);
        }
    } else {
        uint4 z = make_uint4(0, 0, 0, 0);
#pragma unroll
        for (int d = 0; d < DIM; d += 8) {
            *(uint4*)&g_Vh[k * DIM + d] = z;
            *(uint4*)&g_Vl[k * DIM + d] = z;
        }
    }
}

// ---------------------------------------------------------------------------
// Kernel C2: gather + transpose ES -> ES^T fp16 [128 bd][NPAD i].
// grid 130 x 256, tile 64 i x 128 bd, vectorized uint4 stores.
// ---------------------------------------------------------------------------
__global__ void gatherE_kernel() {
    __shared__ __half sh[64 * 130];  // [64 k][130 bd]
    int c = blockIdx.x, t = threadIdx.x;
    int cnt = g_count;
#pragma unroll
    for (int it = 0; it < 32; it++) {
        int idx = it * 256 + t;
        int k = idx >> 7, bd = idx & 127;
        int gi = c * 64 + k;
        float v = 0.0f;
        if (gi < cnt) {
            int src = g_active[gi];
            v = g_ES[bd >> 6][src * DIM + (bd & 63)];
        }
        sh[k * 130 + bd] = __float2half_rn(v);
    }
    __syncthreads();
    const int r = t >> 1, half = t & 1;
    const int kbase = half * 32;
    const int ibase = c * 64 + kbase;
#pragma unroll
    for (int kk = 0; kk < 32; kk += 8) {
        uint4 v;
        uint32_t* vp = (uint32_t*)&v;
#pragma unroll
        for (int m = 0; m < 4; m++) {
            int k0 = kbase + kk + 2 * m;
            vp[m] = (uint32_t)__half_as_ushort(sh[k0 * 130 + r]) |
                    ((uint32_t)__half_as_ushort(sh[(k0 + 1) * 130 + r]) << 16);
        }
        *(uint4*)&g_E[r * NPAD + ibase + kk] = v;
    }
}

// ---------------------------------------------------------------------------
// Main HMMA kernel. grid (64 j-tiles, SPLIT) x 256 threads (8 warps).
// ---------------------------------------------------------------------------
#define SM_UL  18432
#define SM_V(s)  (36864 + (s) * 36864)
#define SM_E(s)  (110592 + (s) * 34816)
#define SMEM_MAIN 180224

__device__ __forceinline__ void prefetch_tile(char* sm, uint32_t sb, int s, int i0, int t) {
    uint32_t vh = sb + SM_V(s), vl = vh + SM_UL, eb = sb + SM_E(s);
#pragma unroll
    for (int it = 0; it < 4; it++) {
        int idx = it * 256 + t;
        int row = idx >> 3, ch = idx & 7;
        uint32_t doff = (uint32_t)(row * 144 + ch * 16);
        CP16(vh + doff, (const char*)&g_Vh[(i0 + row) * DIM + ch * 8]);
        CP16(vl + doff, (const char*)&g_Vl[(i0 + row) * DIM + ch * 8]);
    }
#pragma unroll
    for (int it = 0; it < 8; it++) {
        int idx = it * 256 + t;
        int row = idx >> 4, ch = idx & 15;
        CP16(eb + (uint32_t)(row * 272 + ch * 16),
             (const char*)&g_E[row * NPAD + i0 + ch * 8]);
    }
}

__global__ void __launch_bounds__(256, 1)
main_mma(const float* __restrict__ bias) {
    extern __shared__ char sm[];
    const uint32_t sb = smem_u32(sm);
    const int t = threadIdx.x;
    const int w = t >> 5, lane = t & 31;
    const int gid = lane >> 2, tig = lane & 3;
    const int jt = blockIdx.x, part = blockIdx.y;
    const int j0 = jt * 128;
    const float bb = bias[0];

    __half* u_h = (__half*)sm;
    __half* u_l = (__half*)(sm + SM_UL);

    const int cnt = g_count;
    const int nT = (cnt + 127) >> 7;
    const int t0 = (part * nT) / SPLIT;
    const int t1 = ((part + 1) * nT) / SPLIT;
    const int Tl = t1 - t0;

#pragma unroll
    for (int it = 0; it < 4; it++) {
        int idx = it * 256 + t;
        int row = idx >> 3, ch = idx & 7;
        *(uint4*)(u_h + row * 72 + ch * 8) = *(const uint4*)&g_Uh[(j0 + row) * DIM + ch * 8];
        *(uint4*)(u_l + row * 72 + ch * 8) = *(const uint4*)&g_Ul[(j0 + row) * DIM + ch * 8];
    }

    float acc2[16][4];
#pragma unroll
    for (int nt = 0; nt < 16; nt++)
#pragma unroll
        for (int q = 0; q < 4; q++) acc2[nt][q] = 0.0f;

    if (Tl > 0) {
        prefetch_tile(sm, sb, 0, t0 * 128, t);
        CP_COMMIT();
    }
    __syncthreads();

    uint32_t au[4][4], al[4][4];
    {
        const __half* ubase_h = u_h + (16 * w + gid) * 72 + 2 * tig;
        const __half* ubase_l = u_l + (16 * w + gid) * 72 + 2 * tig;
#pragma unroll
        for (int kk = 0; kk < 4; kk++) {
            const __half* ph = ubase_h + 16 * kk;
            const __half* pl = ubase_l + 16 * kk;
            au[kk][0] = *(const uint32_t*)ph;
            au[kk][1] = *(const uint32_t*)(ph + 8 * 72);
            au[kk][2] = *(const uint32_t*)(ph + 8);
            au[kk][3] = *(const uint32_t*)(ph + 8 * 72 + 8);
            al[kk][0] = *(const uint32_t*)pl;
            al[kk][1] = *(const uint32_t*)(pl + 8 * 72);
            al[kk][2] = *(const uint32_t*)(pl + 8);
            al[kk][3] = *(const uint32_t*)(pl + 8 * 72 + 8);
        }
    }

    for (int lt = 0; lt < Tl; lt++) {
        const int s = lt & 1;
        if (lt + 1 < Tl) {
            prefetch_tile(sm, sb, s ^ 1, (t0 + lt + 1) * 128, t);
            CP_COMMIT();
            CP_WAIT(1);
        } else {
            CP_WAIT(0);
        }
        __syncthreads();

        const __half* vh = (const __half*)(sm + SM_V(s));
        const __half* vl = vh + SM_UL / 2;
        const __half* eb = (const __half*)(sm + SM_E(s));

        // GEMM1 + sigmoid + pack: two independent accumulator chains per n8 tile
        uint32_t ra[8][4];
#pragma unroll
        for (int q = 0; q < 8; q++) {
            float pa[2][4], pb[2][4];
#pragma unroll
            for (int ss = 0; ss < 2; ss++) {
#pragma unroll
                for (int z = 0; z < 4; z++) { pa[ss][z] = 0.0f; pb[ss][z] = 0.0f; }
                const int nt = 2 * q + ss;
                const __half* vrow_h = vh + (8 * nt + gid) * 72 + 2 * tig;
                const __half* vrow_l = vl + (8 * nt + gid) * 72 + 2 * tig;
#pragma unroll
                for (int kk = 0; kk < 4; kk++) {
                    uint32_t bh0 = *(const uint32_t*)(vrow_h + 16 * kk);
                    uint32_t bh1 = *(const uint32_t*)(vrow_h + 16 * kk + 8);
                    uint32_t bl0 = *(const uint32_t*)(vrow_l + 16 * kk);
                    uint32_t bl1 = *(const uint32_t*)(vrow_l + 16 * kk + 8);
                    MMA16816(pa[ss], au[kk], bh0, bh1);   // hi*hi chain
                    MMA16816(pb[ss], al[kk], bh0, bh1);   // cross chain (independent)
                    MMA16816(pb[ss], au[kk], bl0, bl1);
                }
            }
            ra[q][0] = packh2(sigmf(pa[0][0] + pb[0][0] + bb), sigmf(pa[0][1] + pb[0][1] + bb));
            ra[q][1] = packh2(sigmf(pa[0][2] + pb[0][2] + bb), sigmf(pa[0][3] + pb[0][3] + bb));
            ra[q][2] = packh2(sigmf(pa[1][0] + pb[1][0] + bb), sigmf(pa[1][1] + pb[1][1] + bb));
            ra[q][3] = packh2(sigmf(pa[1][2] + pb[1][2] + bb), sigmf(pa[1][3] + pb[1][3] + bb));
        }

        // GEMM2: leaked[16j x 128bd] += P[16j x 128i] * E^T[128i x 128bd]
#pragma unroll
        for (int nt = 0; nt < 16; nt++) {
            const __half* erow = eb + (8 * nt + gid) * 136 + 2 * tig;
#pragma unroll
            for (int q = 0; q < 8; q++) {
                uint32_t b0 = *(const uint32_t*)(erow + 16 * q);
                uint32_t b1 = *(const uint32_t*)(erow + 16 * q + 8);
                MMA16816(acc2[nt], ra[q], b0, b1);
            }
        }
        __syncthreads();
    }

    {
        const int j = j0 + 16 * w + gid;
        float* dst0 = &g_part[part][(size_t)j * 128];
        float* dst1 = &g_part[part][(size_t)(j + 8) * 128];
#pragma unroll
        for (int nt = 0; nt < 16; nt++) {
            const int bd = 8 * nt + 2 * tig;
            *(float2*)(dst0 + bd) = make_float2(acc2[nt][0], acc2[nt][1]);
            *(float2*)(dst1 + bd) = make_float2(acc2[nt][2], acc2[nt][3]);
        }
    }
}

// ---------------------------------------------------------------------------
// Combine: out = S + part0 + part1 - diag * ES. grid 1024 x 256 (float4).
// ---------------------------------------------------------------------------
__global__ void combine_kernel(const float* __restrict__ S, float* __restrict__ out) {
    int f = blockIdx.x * blockDim.x + threadIdx.x;
    int e = f * 4;
    int b = e >> 19;
    int r = (e >> 6) & (NT - 1);
    int d = e & 63;
    float4 s4 = *(const float4*)&S[e];
    float4 a0 = *(const float4*)&g_part[0][(size_t)r * 128 + b * 64 + d];
    float4 a1 = *(const float4*)&g_part[1][(size_t)r * 128 + b * 64 + d];
    float dj = g_diag[r];
    float4 e4 = *(const float4*)&g_ES[b][r * DIM + d];
    float4 o;
    o.x = s4.x + (a0.x + a1.x) - dj * e4.x;
    o.y = s4.y + (a0.y + a1.y) - dj * e4.y;
    o.z = s4.z + (a0.z + a1.z) - dj * e4.z;
    o.w = s4.w + (a0.w + a1.w) - dj * e4.w;
    *(float4*)&out[e] = o;
}

// ---------------------------------------------------------------------------
extern "C" void kernel_launch(void* const* d_in, const int* in_sizes, int n_in,
                              void* d_out, int out_size) {
    const float* S    = (const float*)d_in[0];
    const float* prof = (const float*)d_in[1];
    const float* U    = (const float*)d_in[2];
    const float* W    = (const float*)d_in[3];
    const float* bias = (const float*)d_in[4];
    float* out = (float*)d_out;

    cudaFuncSetAttribute(main_mma, cudaFuncAttributeMaxDynamicSharedMemorySize, SMEM_MAIN);

    precompute_kernel<<<64, 256>>>(S, prof, U, W, bias);
    scan_kernel<<<1, 256>>>();
    gatherV_kernel<<<65, 128>>>();
    gatherE_kernel<<<130, 256>>>();
    main_mma<<<dim3(64, SPLIT), 256, SMEM_MAIN>>>(bias);
    combine_kernel<<<1024, 256>>>(S, out);
}

// round 8
// speedup vs baseline: 9.8322x; 1.0982x over previous
#include <cuda_runtime.h>
#include <cuda_fp16.h>
#include <cstdint>

#define NT 8192
#define DIM 64
#define THRESH 0.7f
#define NPAD 8320          // 65 * 128
#define SPLIT 2

// ---------------- global scratch (static, no allocation) ----------------
__device__ float g_V[NT * DIM];
__device__ float g_diag[NT];
__device__ float g_ES[2][NT * DIM];
__device__ __half g_Uh[NT * DIM], g_Ul[NT * DIM];      // U split hi/lo
__device__ __half g_Vh[NPAD * DIM], g_Vl[NPAD * DIM];  // compacted V split hi/lo
__device__ __half g_Ec[(size_t)NPAD * 128];            // compacted ES rows: [i][bd], bd=b*64+d
__device__ float g_part[SPLIT][NT * 128];
__device__ int g_active[NT];
__device__ int g_count;
__device__ int g_flag[NT];
__device__ int g_done[64];

// ---------------- helpers ----------------
__device__ __forceinline__ uint32_t smem_u32(const void* p) {
    uint32_t a;
    asm("{ .reg .u64 t; cvta.to.shared.u64 t, %1; cvt.u32.u64 %0, t; }" : "=r"(a) : "l"(p));
    return a;
}
#define CP16(d, s) asm volatile("cp.async.cg.shared.global [%0], [%1], 16;" :: "r"(d), "l"(s) : "memory")
#define CP_COMMIT() asm volatile("cp.async.commit_group;" ::: "memory")
#define CP_WAIT(n) asm volatile("cp.async.wait_group %0;" :: "n"(n) : "memory")

#define MMA16816(c, a, b0, b1) \
    asm volatile("mma.sync.aligned.m16n8k16.row.col.f32.f16.f16.f32 " \
                 "{%0,%1,%2,%3}, {%4,%5,%6,%7}, {%8,%9}, {%0,%1,%2,%3};" \
                 : "+f"((c)[0]), "+f"((c)[1]), "+f"((c)[2]), "+f"((c)[3]) \
                 : "r"((a)[0]), "r"((a)[1]), "r"((a)[2]), "r"((a)[3]), \
                   "r"(b0), "r"(b1))

#define LDMX4(r0, r1, r2, r3, addr) \
    asm volatile("ldmatrix.sync.aligned.m8n8.x4.shared.b16 {%0,%1,%2,%3}, [%4];" \
                 : "=r"(r0), "=r"(r1), "=r"(r2), "=r"(r3) : "r"(addr))
#define LDMX4T(r0, r1, r2, r3, addr) \
    asm volatile("ldmatrix.sync.aligned.m8n8.x4.trans.shared.b16 {%0,%1,%2,%3}, [%4];" \
                 : "=r"(r0), "=r"(r1), "=r"(r2), "=r"(r3) : "r"(addr))

__device__ __forceinline__ float sigm(float x) { return 1.0f / (1.0f + __expf(-x)); }
__device__ __forceinline__ float sigmf(float x) {
    return __fdividef(1.0f, 1.0f + __expf(-x));
}
__device__ __forceinline__ uint32_t packh2(float x, float y) {
    __half2 h = __floats2half2_rn(x, y);
    return *(uint32_t*)&h;
}
__device__ __forceinline__ uint32_t packsplit_h(float x, float y, uint32_t& lo) {
    __half hx = __float2half_rn(x), hy = __float2half_rn(y);
    __half lx = __float2half_rn(x - __half2float(hx));
    __half ly = __float2half_rn(y - __half2float(hy));
    lo = (uint32_t)__half_as_ushort(lx) | ((uint32_t)__half_as_ushort(ly) << 16);
    return (uint32_t)__half_as_ushort(hx) | ((uint32_t)__half_as_ushort(hy) << 16);
}

// ---------------------------------------------------------------------------
// Kernel A: per-row precompute + fp16 split of U. grid 64 x 256 (2 thr/row).
// ---------------------------------------------------------------------------
__global__ void precompute_kernel(const float* __restrict__ S,
                                  const float* __restrict__ prof,
                                  const float* __restrict__ U,
                                  const float* __restrict__ W,
                                  const float* __restrict__ bias) {
    __shared__ float Wsm[DIM * DIM];
    int t = threadIdx.x;
    for (int idx = t; idx < DIM * DIM; idx += blockDim.x) Wsm[idx] = W[idx];
    __syncthreads();

    const int half = t & 1;
    const int i = blockIdx.x * 128 + (t >> 1);

    float u[DIM];
#pragma unroll
    for (int e = 0; e < DIM; e += 4) {
        float4 v4 = *(const float4*)&U[i * DIM + e];
        u[e] = v4.x; u[e + 1] = v4.y; u[e + 2] = v4.z; u[e + 3] = v4.w;
    }

    float dacc = 0.0f;
    const int f0 = half * 32;
#pragma unroll 4
    for (int fo = 0; fo < 32; fo++) {
        int f = f0 + fo;
        float s = 0.0f;
#pragma unroll
        for (int e = 0; e < DIM; e++) s += u[e] * Wsm[e * DIM + f];
        g_V[i * DIM + f] = s;
        dacc += s * u[f];
    }
    dacc += __shfl_xor_sync(0xffffffffu, dacc, 1);
    if (half == 0) g_diag[i] = sigm(dacc + bias[0]);

#pragma unroll
    for (int d = f0; d < f0 + 32; d += 2) {
        uint32_t lo, hi = packsplit_h(u[d], u[d + 1], lo);
        *(uint32_t*)&g_Uh[i * DIM + d] = hi;
        *(uint32_t*)&g_Ul[i * DIM + d] = lo;
    }

    float gg = fmaxf(prof[half * NT + i] - THRESH, 0.0f);
    float go = __shfl_xor_sync(0xffffffffu, gg, 1);
    if (half == 0) g_flag[i] = (gg > 0.0f || go > 0.0f) ? 1 : 0;

#pragma unroll
    for (int d = 0; d < DIM; d += 4) {
        size_t src = (size_t)half * NT * DIM + i * DIM + d;
        float4 s4 = *(const float4*)&S[src];
        float4 e4 = make_float4(gg * s4.x, gg * s4.y, gg * s4.z, gg * s4.w);
        *(float4*)&g_ES[half][i * DIM + d] = e4;
    }
}

// ---------------------------------------------------------------------------
// Kernel B: deterministic compaction scan (Hillis-Steele) + g_done reset.
// ---------------------------------------------------------------------------
__global__ void scan_kernel() {
    __shared__ int sums[256];
    int t = threadIdx.x;
    if (t < 64) g_done[t] = 0;
    const int CH = NT / 256;  // 32
    int base = t * CH;
    int flags[CH];
    int s = 0;
#pragma unroll
    for (int k = 0; k < CH; k++) { flags[k] = g_flag[base + k]; s += flags[k]; }
    sums[t] = s;
    __syncthreads();
#pragma unroll
    for (int off = 1; off < 256; off <<= 1) {
        int v = (t >= off) ? sums[t - off] : 0;
        __syncthreads();
        sums[t] += v;
        __syncthreads();
    }
    if (t == 255) g_count = sums[255];
    int o = sums[t] - s;
#pragma unroll
    for (int k = 0; k < CH; k++)
        if (flags[k]) g_active[o++] = base + k;
}

// ---------------------------------------------------------------------------
// Kernel C: merged gather. 8 threads per compacted row. grid 260 x 256.
//   p 0..3: V split hi/lo, 16 d each.  p 4..7: ES row fp16, 32 bd each.
// ---------------------------------------------------------------------------
__global__ void gather_kernel() {
    int gid = blockIdx.x * 256 + threadIdx.x;
    int k = gid >> 3, p = gid & 7;
    int cnt = g_count;
    if (k < cnt) {
        int src = g_active[k];
        if (p < 4) {
            const int d0 = p * 16;
#pragma unroll
            for (int dd = 0; dd < 16; dd += 4) {
                float4 v4 = *(const float4*)&g_V[src * DIM + d0 + dd];
                uint2 hv, lv;
                hv.x = packsplit_h(v4.x, v4.y, lv.x);
                hv.y = packsplit_h(v4.z, v4.w, lv.y);
                *(uint2*)&g_Vh[k * DIM + d0 + dd] = hv;
                *(uint2*)&g_Vl[k * DIM + d0 + dd] = lv;
            }
        } else {
            const int bd0 = (p - 4) * 32;
            const int b = bd0 >> 6, dbase = bd0 & 63;
#pragma unroll
            for (int dd = 0; dd < 32; dd += 4) {
                float4 v4 = *(const float4*)&g_ES[b][src * DIM + dbase + dd];
                uint2 hv;
                hv.x = packh2(v4.x, v4.y);
                hv.y = packh2(v4.z, v4.w);
                *(uint2*)&g_Ec[(size_t)k * 128 + bd0 + dd] = hv;
            }
        }
    } else {
        if (p < 4) {
            const int d0 = p * 16;
            uint4 z = make_uint4(0, 0, 0, 0);
#pragma unroll
            for (int dd = 0; dd < 16; dd += 8) {
                *(uint4*)&g_Vh[k * DIM + d0 + dd] = z;
                *(uint4*)&g_Vl[k * DIM + d0 + dd] = z;
            }
        } else {
            const int bd0 = (p - 4) * 32;
            uint4 z = make_uint4(0, 0, 0, 0);
#pragma unroll
            for (int dd = 0; dd < 32; dd += 8)
                *(uint4*)&g_Ec[(size_t)k * 128 + bd0 + dd] = z;
        }
    }
}

// ---------------------------------------------------------------------------
// Main HMMA kernel. grid (64 j-tiles, SPLIT) x 256 threads (8 warps).
// V tile [128 i][72h pitch]; E tile [128 i][136h pitch] natural layout.
// GEMM1 B via ldmatrix.x4; GEMM2 B via ldmatrix.x4.trans.
// ---------------------------------------------------------------------------
#define SM_UL  18432
#define SM_V(s)  (36864 + (s) * 36864)
#define SM_E(s)  (110592 + (s) * 34816)
#define SMEM_MAIN 180224

__device__ __forceinline__ void prefetch_tile(uint32_t sb, int s, int i0, int t) {
    uint32_t vh = sb + SM_V(s), vl = vh + SM_UL, eb = sb + SM_E(s);
#pragma unroll
    for (int it = 0; it < 4; it++) {
        int idx = it * 256 + t;
        int row = idx >> 3, ch = idx & 7;
        uint32_t doff = (uint32_t)(row * 144 + ch * 16);
        CP16(vh + doff, (const char*)&g_Vh[(i0 + row) * DIM + ch * 8]);
        CP16(vl + doff, (const char*)&g_Vl[(i0 + row) * DIM + ch * 8]);
    }
#pragma unroll
    for (int it = 0; it < 8; it++) {
        int idx = it * 256 + t;
        int row = idx >> 4, ch = idx & 15;
        CP16(eb + (uint32_t)(row * 272 + ch * 16),
             (const char*)&g_Ec[(size_t)(i0 + row) * 128 + ch * 8]);
    }
}

__global__ void __launch_bounds__(256, 1)
main_mma(const float* __restrict__ bias, const float* __restrict__ S,
         float* __restrict__ out) {
    extern __shared__ char sm[];
    const uint32_t sb = smem_u32(sm);
    const int t = threadIdx.x;
    const int w = t >> 5, lane = t & 31;
    const int gid = lane >> 2, tig = lane & 3;
    const int jt = blockIdx.x, part = blockIdx.y;
    const int j0 = jt * 128;
    const float bb = bias[0];

    __half* u_h = (__half*)sm;
    __half* u_l = (__half*)(sm + SM_UL);

    const int cnt = g_count;
    const int nT = (cnt + 127) >> 7;
    const int t0 = (part * nT) / SPLIT;
    const int t1 = ((part + 1) * nT) / SPLIT;
    const int Tl = t1 - t0;

#pragma unroll
    for (int it = 0; it < 4; it++) {
        int idx = it * 256 + t;
        int row = idx >> 3, ch = idx & 7;
        *(uint4*)(u_h + row * 72 + ch * 8) = *(const uint4*)&g_Uh[(j0 + row) * DIM + ch * 8];
        *(uint4*)(u_l + row * 72 + ch * 8) = *(const uint4*)&g_Ul[(j0 + row) * DIM + ch * 8];
    }

    float acc2[16][4];
#pragma unroll
    for (int nt = 0; nt < 16; nt++)
#pragma unroll
        for (int q = 0; q < 4; q++) acc2[nt][q] = 0.0f;

    if (Tl > 0) {
        prefetch_tile(sb, 0, t0 * 128, t);
        CP_COMMIT();
    }
    __syncthreads();

    // persistent A fragments of U (hi and lo) for the 4 k-chunks
    uint32_t au[4][4], al[4][4];
    {
        const __half* ubase_h = u_h + (16 * w + gid) * 72 + 2 * tig;
        const __half* ubase_l = u_l + (16 * w + gid) * 72 + 2 * tig;
#pragma unroll
        for (int kk = 0; kk < 4; kk++) {
            const __half* ph = ubase_h + 16 * kk;
            const __half* pl = ubase_l + 16 * kk;
            au[kk][0] = *(const uint32_t*)ph;
            au[kk][1] = *(const uint32_t*)(ph + 8 * 72);
            au[kk][2] = *(const uint32_t*)(ph + 8);
            au[kk][3] = *(const uint32_t*)(ph + 8 * 72 + 8);
            al[kk][0] = *(const uint32_t*)pl;
            al[kk][1] = *(const uint32_t*)(pl + 8 * 72);
            al[kk][2] = *(const uint32_t*)(pl + 8);
            al[kk][3] = *(const uint32_t*)(pl + 8 * 72 + 8);
        }
    }

    // per-lane ldmatrix address offsets
    const uint32_t flb_v = (uint32_t)((lane & 15) * 144 + (lane >> 4) * 16);
    const uint32_t flb_e = (uint32_t)((lane & 15) * 272 + (lane >> 4) * 16);

    for (int lt = 0; lt < Tl; lt++) {
        const int s = lt & 1;
        if (lt + 1 < Tl) {
            prefetch_tile(sb, s ^ 1, (t0 + lt + 1) * 128, t);
            CP_COMMIT();
            CP_WAIT(1);
        } else {
            CP_WAIT(0);
        }
        __syncthreads();

        const uint32_t vhb = sb + SM_V(s) + flb_v;
        const uint32_t vlb = vhb + SM_UL;
        const uint32_t ebb = sb + SM_E(s) + flb_e;

        // GEMM1 + sigmoid + pack: P fragments for GEMM2 stay in registers
        uint32_t ra[8][4];
#pragma unroll
        for (int q = 0; q < 8; q++) {
            float pa[2][4], pb[2][4];
#pragma unroll
            for (int z = 0; z < 4; z++) {
                pa[0][z] = 0.0f; pa[1][z] = 0.0f;
                pb[0][z] = 0.0f; pb[1][z] = 0.0f;
            }
#pragma unroll
            for (int kk = 0; kk < 4; kk++) {
                uint32_t h0, h1, h2, h3, l0, l1, l2, l3;
                LDMX4(h0, h1, h2, h3, vhb + q * 2304 + kk * 32);
                LDMX4(l0, l1, l2, l3, vlb + q * 2304 + kk * 32);
                MMA16816(pa[0], au[kk], h0, h2);   // hi*hi chain (ss=0)
                MMA16816(pa[1], au[kk], h1, h3);   // hi*hi chain (ss=1)
                MMA16816(pb[0], al[kk], h0, h2);   // cross chains (independent)
                MMA16816(pb[1], al[kk], h1, h3);
                MMA16816(pb[0], au[kk], l0, l2);
                MMA16816(pb[1], au[kk], l1, l3);
            }
            ra[q][0] = packh2(sigmf(pa[0][0] + pb[0][0] + bb), sigmf(pa[0][1] + pb[0][1] + bb));
            ra[q][1] = packh2(sigmf(pa[0][2] + pb[0][2] + bb), sigmf(pa[0][3] + pb[0][3] + bb));
            ra[q][2] = packh2(sigmf(pa[1][0] + pb[1][0] + bb), sigmf(pa[1][1] + pb[1][1] + bb));
            ra[q][3] = packh2(sigmf(pa[1][2] + pb[1][2] + bb), sigmf(pa[1][3] + pb[1][3] + bb));
        }

        // GEMM2: leaked[16j x 128bd] += P[16j x 128i] * E[128i x 128bd]
        //        B fragments via ldmatrix.trans from natural [i][bd] tile
#pragma unroll
        for (int ntp = 0; ntp < 8; ntp++) {
#pragma unroll
            for (int q = 0; q < 8; q++) {
                uint32_t e0, e1, e2, e3;
                LDMX4T(e0, e1, e2, e3, ebb + q * 4352 + ntp * 32);
                MMA16816(acc2[2 * ntp], ra[q], e0, e1);
                MMA16816(acc2[2 * ntp + 1], ra[q], e2, e3);
            }
        }
        __syncthreads();
    }

    // write partial leaked
    {
        const int j = j0 + 16 * w + gid;
        float* dst0 = &g_part[part][(size_t)j * 128];
        float* dst1 = &g_part[part][(size_t)(j + 8) * 128];
#pragma unroll
        for (int nt = 0; nt < 16; nt++) {
            const int bd = 8 * nt + 2 * tig;
            *(float2*)(dst0 + bd) = make_float2(acc2[nt][0], acc2[nt][1]);
            *(float2*)(dst1 + bd) = make_float2(acc2[nt][2], acc2[nt][3]);
        }
    }

    // deterministic ticket: second CTA of this jt does the combine
    __threadfence();
    __syncthreads();
    volatile int* flag = (volatile int*)sm;
    if (t == 0) *(int*)sm = atomicAdd(&g_done[jt], 1);
    __syncthreads();
    if (*flag == 1) {
        // out = S + part0 + part1 - diag * ES   for j rows of this jt
#pragma unroll
        for (int it = 0; it < 16; it++) {
            int idx = it * 256 + t;
            int j = idx >> 5;            // 0..127
            int c4 = idx & 31;           // float4 index within 128 bd
            int bd = c4 * 4;
            int b = bd >> 6, d = bd & 63;
            int jg = j0 + j;
            float4 a0 = *(const float4*)&g_part[0][(size_t)jg * 128 + bd];
            float4 a1 = *(const float4*)&g_part[1][(size_t)jg * 128 + bd];
            size_t oi = ((size_t)b * NT + jg) * DIM + d;
            float4 s4 = *(const float4*)&S[oi];
            float dj = g_diag[jg];
            float4 e4 = *(const float4*)&g_ES[b][jg * DIM + d];
            float4 o;
            o.x = s4.x + (a0.x + a1.x) - dj * e4.x;
            o.y = s4.y + (a0.y + a1.y) - dj * e4.y;
            o.z = s4.z + (a0.z + a1.z) - dj * e4.z;
            o.w = s4.w + (a0.w + a1.w) - dj * e4.w;
            *(float4*)&out[oi] = o;
        }
    }
}

// ---------------------------------------------------------------------------
extern "C" void kernel_launch(void* const* d_in, const int* in_sizes, int n_in,
                              void* d_out, int out_size) {
    const float* S    = (const float*)d_in[0];
    const float* prof = (const float*)d_in[1];
    const float* U    = (const float*)d_in[2];
    const float* W    = (const float*)d_in[3];
    const float* bias = (const float*)d_in[4];
    float* out = (float*)d_out;

    cudaFuncSetAttribute(main_mma, cudaFuncAttributeMaxDynamicSharedMemorySize, SMEM_MAIN);

    precompute_kernel<<<64, 256>>>(S, prof, U, W, bias);
    scan_kernel<<<1, 256>>>();
    gather_kernel<<<260, 256>>>();
    main_mma<<<dim3(64, SPLIT), 256, SMEM_MAIN>>>(bias, S, out);
}

// round 9
// speedup vs baseline: 10.3018x; 1.0478x over previous
#include <cuda_runtime.h>
#include <cuda_fp16.h>
#include <cstdint>

#define NT 8192
#define DIM 64
#define THRESH 0.7f
#define SPLIT 2

// ---------------- global scratch (static, no allocation) ----------------
__device__ float g_diag[NT];
__device__ float g_ES[2][NT * DIM];                    // fp32 gated states (combine epilogue)
__device__ __half g_Uh[NT * DIM], g_Ul[NT * DIM];      // U split hi/lo
__device__ __half g_Vh[NT * DIM], g_Vl[NT * DIM];      // V split hi/lo (uncompacted)
__device__ __half g_Ef[(size_t)NT * 128];              // ES fp16 rows: [i][bd], bd=b*64+d
__device__ float g_part[SPLIT][NT * 128];
__device__ int g_active[NT];
__device__ int g_count;
__device__ int g_flag[NT];
__device__ int g_done[64];

// ---------------- helpers ----------------
__device__ __forceinline__ uint32_t smem_u32(const void* p) {
    uint32_t a;
    asm("{ .reg .u64 t; cvta.to.shared.u64 t, %1; cvt.u32.u64 %0, t; }" : "=r"(a) : "l"(p));
    return a;
}
#define CP16Z(d, s, n) \
    asm volatile("cp.async.cg.shared.global [%0], [%1], 16, %2;" \
                 :: "r"(d), "l"(s), "r"(n) : "memory")
#define CP_COMMIT() asm volatile("cp.async.commit_group;" ::: "memory")
#define CP_WAIT(n) asm volatile("cp.async.wait_group %0;" :: "n"(n) : "memory")

#define MMA16816(c, a, b0, b1) \
    asm volatile("mma.sync.aligned.m16n8k16.row.col.f32.f16.f16.f32 " \
                 "{%0,%1,%2,%3}, {%4,%5,%6,%7}, {%8,%9}, {%0,%1,%2,%3};" \
                 : "+f"((c)[0]), "+f"((c)[1]), "+f"((c)[2]), "+f"((c)[3]) \
                 : "r"((a)[0]), "r"((a)[1]), "r"((a)[2]), "r"((a)[3]), \
                   "r"(b0), "r"(b1))

#define LDMX4(r0, r1, r2, r3, addr) \
    asm volatile("ldmatrix.sync.aligned.m8n8.x4.shared.b16 {%0,%1,%2,%3}, [%4];" \
                 : "=r"(r0), "=r"(r1), "=r"(r2), "=r"(r3) : "r"(addr))
#define LDMX4T(r0, r1, r2, r3, addr) \
    asm volatile("ldmatrix.sync.aligned.m8n8.x4.trans.shared.b16 {%0,%1,%2,%3}, [%4];" \
                 : "=r"(r0), "=r"(r1), "=r"(r2), "=r"(r3) : "r"(addr))

__device__ __forceinline__ float sigm(float x) { return 1.0f / (1.0f + __expf(-x)); }
__device__ __forceinline__ float sigmf(float x) {
    return __fdividef(1.0f, 1.0f + __expf(-x));
}
__device__ __forceinline__ uint32_t packh2(float x, float y) {
    __half2 h = __floats2half2_rn(x, y);
    return *(uint32_t*)&h;
}
__device__ __forceinline__ uint32_t packsplit_h(float x, float y, uint32_t& lo) {
    __half hx = __float2half_rn(x), hy = __float2half_rn(y);
    __half lx = __float2half_rn(x - __half2float(hx));
    __half ly = __float2half_rn(y - __half2float(hy));
    lo = (uint32_t)__half_as_ushort(lx) | ((uint32_t)__half_as_ushort(ly) << 16);
    return (uint32_t)__half_as_ushort(hx) | ((uint32_t)__half_as_ushort(hy) << 16);
}

// ---------------------------------------------------------------------------
// Kernel A: per-row precompute. grid 128 x 256 (4 threads/row).
//   thread p=t&3: V cols [16p,16p+16), U split d in [16p,16p+16),
//   ES batch p>>1, d-half (p&1)*32.
// ---------------------------------------------------------------------------
__global__ void precompute_kernel(const float* __restrict__ S,
                                  const float* __restrict__ prof,
                                  const float* __restrict__ U,
                                  const float* __restrict__ W,
                                  const float* __restrict__ bias) {
    __shared__ float Wsm[DIM * DIM];
    int t = threadIdx.x;
    for (int idx = t; idx < DIM * DIM; idx += blockDim.x) Wsm[idx] = W[idx];
    __syncthreads();

    const int p = t & 3;
    const int i = blockIdx.x * 64 + (t >> 2);

    float u[DIM];
#pragma unroll
    for (int e = 0; e < DIM; e += 4) {
        float4 v4 = *(const float4*)&U[i * DIM + e];
        u[e] = v4.x; u[e + 1] = v4.y; u[e + 2] = v4.z; u[e + 3] = v4.w;
    }

    // V columns [16p, 16p+16): compute, split to fp16 hi/lo, partial diag dot
    float dacc = 0.0f;
    const int f0 = p * 16;
#pragma unroll 2
    for (int fo = 0; fo < 16; fo += 2) {
        int f = f0 + fo;
        float s0 = 0.0f, s1 = 0.0f;
#pragma unroll
        for (int e = 0; e < DIM; e++) {
            s0 += u[e] * Wsm[e * DIM + f];
            s1 += u[e] * Wsm[e * DIM + f + 1];
        }
        dacc += s0 * u[f] + s1 * u[f + 1];
        uint32_t lo, hi = packsplit_h(s0, s1, lo);
        *(uint32_t*)&g_Vh[i * DIM + f] = hi;
        *(uint32_t*)&g_Vl[i * DIM + f] = lo;
    }
    dacc += __shfl_xor_sync(0xffffffffu, dacc, 1);
    dacc += __shfl_xor_sync(0xffffffffu, dacc, 2);
    if (p == 0) g_diag[i] = sigm(dacc + bias[0]);

    // U split hi/lo for d in [16p, 16p+16)
#pragma unroll
    for (int d = f0; d < f0 + 16; d += 2) {
        uint32_t lo, hi = packsplit_h(u[d], u[d + 1], lo);
        *(uint32_t*)&g_Uh[i * DIM + d] = hi;
        *(uint32_t*)&g_Ul[i * DIM + d] = lo;
    }

    // gating + ES: batch b = p>>1, d-half dh = (p&1)*32
    const int b = p >> 1, dh = (p & 1) * 32;
    float gg = fmaxf(prof[b * NT + i] - THRESH, 0.0f);
    float go = __shfl_xor_sync(0xffffffffu, gg, 2);
    if (p == 0) g_flag[i] = (gg > 0.0f || go > 0.0f) ? 1 : 0;

#pragma unroll
    for (int d = dh; d < dh + 32; d += 4) {
        size_t src = (size_t)b * NT * DIM + i * DIM + d;
        float4 s4 = *(const float4*)&S[src];
        float4 e4 = make_float4(gg * s4.x, gg * s4.y, gg * s4.z, gg * s4.w);
        *(float4*)&g_ES[b][i * DIM + d] = e4;
        uint2 hv;
        hv.x = packh2(e4.x, e4.y);
        hv.y = packh2(e4.z, e4.w);
        *(uint2*)&g_Ef[(size_t)i * 128 + b * 64 + d] = hv;
    }
}

// ---------------------------------------------------------------------------
// Kernel B: deterministic compaction scan (Hillis-Steele) + g_done reset.
// ---------------------------------------------------------------------------
__global__ void scan_kernel() {
    __shared__ int sums[256];
    int t = threadIdx.x;
    if (t < 64) g_done[t] = 0;
    const int CH = NT / 256;  // 32
    int base = t * CH;
    int flags[CH];
    int s = 0;
#pragma unroll
    for (int k = 0; k < CH; k++) { flags[k] = g_flag[base + k]; s += flags[k]; }
    sums[t] = s;
    __syncthreads();
#pragma unroll
    for (int off = 1; off < 256; off <<= 1) {
        int v = (t >= off) ? sums[t - off] : 0;
        __syncthreads();
        sums[t] += v;
        __syncthreads();
    }
    if (t == 255) g_count = sums[255];
    int o = sums[t] - s;
#pragma unroll
    for (int k = 0; k < CH; k++)
        if (flags[k]) g_active[o++] = base + k;
}

// ---------------------------------------------------------------------------
// Main HMMA kernel. grid (64 j-tiles, SPLIT) x 256 threads (8 warps).
// Prefetch gathers compacted rows directly via g_active (cp.async zero-fill
// for the tail). GEMM2 interleaved into the GEMM1 q-loop (ra fragment dies
// immediately -> no spills).
// ---------------------------------------------------------------------------
#define SM_UL  18432
#define SM_V(s)  (36864 + (s) * 36864)
#define SM_E(s)  (110592 + (s) * 34816)
#define SMEM_MAIN 180224

__device__ __forceinline__ void prefetch_tile(uint32_t sb, int s, int i0, int t, int cnt) {
    uint32_t vh = sb + SM_V(s), vl = vh + SM_UL, eb = sb + SM_E(s);
#pragma unroll
    for (int it = 0; it < 4; it++) {
        int idx = it * 256 + t;
        int row = idx >> 3, ch = idx & 7;
        int gi = i0 + row;
        int ok = gi < cnt;
        int src = ok ? g_active[gi] : 0;
        int n = ok ? 16 : 0;
        uint32_t doff = (uint32_t)(row * 144 + ch * 16);
        CP16Z(vh + doff, (const char*)&g_Vh[src * DIM + ch * 8], n);
        CP16Z(vl + doff, (const char*)&g_Vl[src * DIM + ch * 8], n);
    }
#pragma unroll
    for (int it = 0; it < 8; it++) {
        int idx = it * 256 + t;
        int row = idx >> 4, ch = idx & 15;
        int gi = i0 + row;
        int ok = gi < cnt;
        int src = ok ? g_active[gi] : 0;
        int n = ok ? 16 : 0;
        CP16Z(eb + (uint32_t)(row * 272 + ch * 16),
              (const char*)&g_Ef[(size_t)src * 128 + ch * 8], n);
    }
}

__global__ void __launch_bounds__(256, 1)
main_mma(const float* __restrict__ bias, const float* __restrict__ S,
         float* __restrict__ out) {
    extern __shared__ char sm[];
    const uint32_t sb = smem_u32(sm);
    const int t = threadIdx.x;
    const int w = t >> 5, lane = t & 31;
    const int gid = lane >> 2, tig = lane & 3;
    const int jt = blockIdx.x, part = blockIdx.y;
    const int j0 = jt * 128;
    const float bb = bias[0];

    __half* u_h = (__half*)sm;
    __half* u_l = (__half*)(sm + SM_UL);

    const int cnt = g_count;
    const int nT = (cnt + 127) >> 7;
    const int t0 = (part * nT) / SPLIT;
    const int t1 = ((part + 1) * nT) / SPLIT;
    const int Tl = t1 - t0;

#pragma unroll
    for (int it = 0; it < 4; it++) {
        int idx = it * 256 + t;
        int row = idx >> 3, ch = idx & 7;
        *(uint4*)(u_h + row * 72 + ch * 8) = *(const uint4*)&g_Uh[(j0 + row) * DIM + ch * 8];
        *(uint4*)(u_l + row * 72 + ch * 8) = *(const uint4*)&g_Ul[(j0 + row) * DIM + ch * 8];
    }

    float acc2[16][4];
#pragma unroll
    for (int nt = 0; nt < 16; nt++)
#pragma unroll
        for (int q = 0; q < 4; q++) acc2[nt][q] = 0.0f;

    if (Tl > 0) {
        prefetch_tile(sb, 0, t0 * 128, t, cnt);
        CP_COMMIT();
    }
    __syncthreads();

    // persistent A fragments of U (hi and lo) for the 4 k-chunks
    uint32_t au[4][4], al[4][4];
    {
        const __half* ubase_h = u_h + (16 * w + gid) * 72 + 2 * tig;
        const __half* ubase_l = u_l + (16 * w + gid) * 72 + 2 * tig;
#pragma unroll
        for (int kk = 0; kk < 4; kk++) {
            const __half* ph = ubase_h + 16 * kk;
            const __half* pl = ubase_l + 16 * kk;
            au[kk][0] = *(const uint32_t*)ph;
            au[kk][1] = *(const uint32_t*)(ph + 8 * 72);
            au[kk][2] = *(const uint32_t*)(ph + 8);
            au[kk][3] = *(const uint32_t*)(ph + 8 * 72 + 8);
            al[kk][0] = *(const uint32_t*)pl;
            al[kk][1] = *(const uint32_t*)(pl + 8 * 72);
            al[kk][2] = *(const uint32_t*)(pl + 8);
            al[kk][3] = *(const uint32_t*)(pl + 8 * 72 + 8);
        }
    }

    const uint32_t flb_v = (uint32_t)((lane & 15) * 144 + (lane >> 4) * 16);
    const uint32_t flb_e = (uint32_t)((lane & 15) * 272 + (lane >> 4) * 16);

    for (int lt = 0; lt < Tl; lt++) {
        const int s = lt & 1;
        if (lt + 1 < Tl) {
            prefetch_tile(sb, s ^ 1, (t0 + lt + 1) * 128, t, cnt);
            CP_COMMIT();
            CP_WAIT(1);
        } else {
            CP_WAIT(0);
        }
        __syncthreads();

        const uint32_t vhb = sb + SM_V(s) + flb_v;
        const uint32_t vlb = vhb + SM_UL;
        const uint32_t ebb = sb + SM_E(s) + flb_e;

        // q = 16-wide i-group: GEMM1 (score+sigmoid) then immediately GEMM2
#pragma unroll
        for (int q = 0; q < 8; q++) {
            float pa[2][4], pb[2][4];
#pragma unroll
            for (int z = 0; z < 4; z++) {
                pa[0][z] = 0.0f; pa[1][z] = 0.0f;
                pb[0][z] = 0.0f; pb[1][z] = 0.0f;
            }
#pragma unroll
            for (int kk = 0; kk < 4; kk++) {
                uint32_t h0, h1, h2, h3, l0, l1, l2, l3;
                LDMX4(h0, h1, h2, h3, vhb + q * 2304 + kk * 32);
                LDMX4(l0, l1, l2, l3, vlb + q * 2304 + kk * 32);
                MMA16816(pa[0], au[kk], h0, h2);
                MMA16816(pa[1], au[kk], h1, h3);
                MMA16816(pb[0], al[kk], h0, h2);
                MMA16816(pb[1], al[kk], h1, h3);
                MMA16816(pb[0], au[kk], l0, l2);
                MMA16816(pb[1], au[kk], l1, l3);
            }
            uint32_t ra[4];
            ra[0] = packh2(sigmf(pa[0][0] + pb[0][0] + bb), sigmf(pa[0][1] + pb[0][1] + bb));
            ra[1] = packh2(sigmf(pa[0][2] + pb[0][2] + bb), sigmf(pa[0][3] + pb[0][3] + bb));
            ra[2] = packh2(sigmf(pa[1][0] + pb[1][0] + bb), sigmf(pa[1][1] + pb[1][1] + bb));
            ra[3] = packh2(sigmf(pa[1][2] + pb[1][2] + bb), sigmf(pa[1][3] + pb[1][3] + bb));

            // GEMM2 contribution of this k16 chunk (i in [16q,16q+16))
#pragma unroll
            for (int ntp = 0; ntp < 8; ntp++) {
                uint32_t e0, e1, e2, e3;
                LDMX4T(e0, e1, e2, e3, ebb + q * 4352 + ntp * 32);
                MMA16816(acc2[2 * ntp], ra, e0, e1);
                MMA16816(acc2[2 * ntp + 1], ra, e2, e3);
            }
        }
        __syncthreads();
    }

    // write partial leaked
    {
        const int j = j0 + 16 * w + gid;
        float* dst0 = &g_part[part][(size_t)j * 128];
        float* dst1 = &g_part[part][(size_t)(j + 8) * 128];
#pragma unroll
        for (int nt = 0; nt < 16; nt++) {
            const int bd = 8 * nt + 2 * tig;
            *(float2*)(dst0 + bd) = make_float2(acc2[nt][0], acc2[nt][1]);
            *(float2*)(dst1 + bd) = make_float2(acc2[nt][2], acc2[nt][3]);
        }
    }

    // deterministic ticket: second CTA of this jt does the combine
    __threadfence();
    __syncthreads();
    volatile int* flag = (volatile int*)sm;
    if (t == 0) *(int*)sm = atomicAdd(&g_done[jt], 1);
    __syncthreads();
    if (*flag == 1) {
#pragma unroll
        for (int it = 0; it < 16; it++) {
            int idx = it * 256 + t;
            int j = idx >> 5;
            int c4 = idx & 31;
            int bd = c4 * 4;
            int b = bd >> 6, d = bd & 63;
            int jg = j0 + j;
            float4 a0 = *(const float4*)&g_part[0][(size_t)jg * 128 + bd];
            float4 a1 = *(const float4*)&g_part[1][(size_t)jg * 128 + bd];
            size_t oi = ((size_t)b * NT + jg) * DIM + d;
            float4 s4 = *(const float4*)&S[oi];
            float dj = g_diag[jg];
            float4 e4 = *(const float4*)&g_ES[b][jg * DIM + d];
            float4 o;
            o.x = s4.x + (a0.x + a1.x) - dj * e4.x;
            o.y = s4.y + (a0.y + a1.y) - dj * e4.y;
            o.z = s4.z + (a0.z + a1.z) - dj * e4.z;
            o.w = s4.w + (a0.w + a1.w) - dj * e4.w;
            *(float4*)&out[oi] = o;
        }
    }
}

// ---------------------------------------------------------------------------
extern "C" void kernel_launch(void* const* d_in, const int* in_sizes, int n_in,
                              void* d_out, int out_size) {
    const float* S    = (const float*)d_in[0];
    const float* prof = (const float*)d_in[1];
    const float* U    = (const float*)d_in[2];
    const float* W    = (const float*)d_in[3];
    const float* bias = (const float*)d_in[4];
    float* out = (float*)d_out;

    cudaFuncSetAttribute(main_mma, cudaFuncAttributeMaxDynamicSharedMemorySize, SMEM_MAIN);

    precompute_kernel<<<128, 256>>>(S, prof, U, W, bias);
    scan_kernel<<<1, 256>>>();
    main_mma<<<dim3(64, SPLIT), 256, SMEM_MAIN>>>(bias, S, out);
}

// round 10
// speedup vs baseline: 13.6800x; 1.3279x over previous
#include <cuda_runtime.h>
#include <cuda_fp16.h>
#include <cstdint>

#define NT 8192
#define DIM 64
#define THRESH 0.7f
#define SPLIT 2

// ---------------- global scratch (static, no allocation) ----------------
__device__ float g_diag[NT];
__device__ float g_ES[2][NT * DIM];                    // fp32 gated states (combine epilogue)
__device__ __half g_Uh[NT * DIM];                      // U fp16
__device__ __half g_Vh[NT * DIM];                      // V fp16 (uncompacted)
__device__ __half g_Ef[(size_t)NT * 128];              // ES fp16 rows: [i][bd], bd=b*64+d
__device__ float g_part[SPLIT][NT * 128];
__device__ int g_active[NT];
__device__ int g_count;
__device__ int g_flag[NT];
__device__ int g_done[64];

// ---------------- helpers ----------------
__device__ __forceinline__ uint32_t smem_u32(const void* p) {
    uint32_t a;
    asm("{ .reg .u64 t; cvta.to.shared.u64 t, %1; cvt.u32.u64 %0, t; }" : "=r"(a) : "l"(p));
    return a;
}
#define CP16Z(d, s, n) \
    asm volatile("cp.async.cg.shared.global [%0], [%1], 16, %2;" \
                 :: "r"(d), "l"(s), "r"(n) : "memory")
#define CP_COMMIT() asm volatile("cp.async.commit_group;" ::: "memory")
#define CP_WAIT(n) asm volatile("cp.async.wait_group %0;" :: "n"(n) : "memory")

#define MMA16816(c, a, b0, b1) \
    asm volatile("mma.sync.aligned.m16n8k16.row.col.f32.f16.f16.f32 " \
                 "{%0,%1,%2,%3}, {%4,%5,%6,%7}, {%8,%9}, {%0,%1,%2,%3};" \
                 : "+f"((c)[0]), "+f"((c)[1]), "+f"((c)[2]), "+f"((c)[3]) \
                 : "r"((a)[0]), "r"((a)[1]), "r"((a)[2]), "r"((a)[3]), \
                   "r"(b0), "r"(b1))

#define LDMX4(r0, r1, r2, r3, addr) \
    asm volatile("ldmatrix.sync.aligned.m8n8.x4.shared.b16 {%0,%1,%2,%3}, [%4];" \
                 : "=r"(r0), "=r"(r1), "=r"(r2), "=r"(r3) : "r"(addr))
#define LDMX4T(r0, r1, r2, r3, addr) \
    asm volatile("ldmatrix.sync.aligned.m8n8.x4.trans.shared.b16 {%0,%1,%2,%3}, [%4];" \
                 : "=r"(r0), "=r"(r1), "=r"(r2), "=r"(r3) : "r"(addr))

__device__ __forceinline__ float sigm(float x) { return 1.0f / (1.0f + __expf(-x)); }
__device__ __forceinline__ float sigmf(float x) {
    return __fdividef(1.0f, 1.0f + __expf(-x));
}
__device__ __forceinline__ uint32_t packh2(float x, float y) {
    __half2 h = __floats2half2_rn(x, y);
    return *(uint32_t*)&h;
}

// ---------------------------------------------------------------------------
// Kernel A: per-row precompute. grid 256 x 256 (8 threads/row).
//   thread p=t&7: V cols [8p,8p+8) (float4 W loads), U fp16 d in [8p,8p+8),
//   ES batch p>>2, d-quarter (p&3)*16.
// ---------------------------------------------------------------------------
__global__ void precompute_kernel(const float* __restrict__ S,
                                  const float* __restrict__ prof,
                                  const float* __restrict__ U,
                                  const float* __restrict__ W,
                                  const float* __restrict__ bias) {
    __shared__ float Wsm[DIM * DIM];
    int t = threadIdx.x;
    for (int idx = t; idx < DIM * DIM / 4; idx += blockDim.x)
        *(float4*)&Wsm[idx * 4] = *(const float4*)&W[idx * 4];
    __syncthreads();

    const int p = t & 7;
    const int i = blockIdx.x * 32 + (t >> 3);

    float u[DIM];
#pragma unroll
    for (int e = 0; e < DIM; e += 4) {
        float4 v4 = *(const float4*)&U[i * DIM + e];
        u[e] = v4.x; u[e + 1] = v4.y; u[e + 2] = v4.z; u[e + 3] = v4.w;
    }

    // V columns [8p, 8p+8): float4 W loads -> 8 FMA per 2 LDS.128
    const int f0 = p * 8;
    float acc[8];
#pragma unroll
    for (int c = 0; c < 8; c++) acc[c] = 0.0f;
    const float4* W4 = (const float4*)Wsm;
#pragma unroll 8
    for (int e = 0; e < DIM; e++) {
        float ue = u[e];
        float4 w0 = W4[e * 16 + p * 2];
        float4 w1 = W4[e * 16 + p * 2 + 1];
        acc[0] += ue * w0.x; acc[1] += ue * w0.y; acc[2] += ue * w0.z; acc[3] += ue * w0.w;
        acc[4] += ue * w1.x; acc[5] += ue * w1.y; acc[6] += ue * w1.z; acc[7] += ue * w1.w;
    }
    float dacc = 0.0f;
#pragma unroll
    for (int c = 0; c < 8; c++) dacc += acc[c] * u[f0 + c];
    dacc += __shfl_xor_sync(0xffffffffu, dacc, 1);
    dacc += __shfl_xor_sync(0xffffffffu, dacc, 2);
    dacc += __shfl_xor_sync(0xffffffffu, dacc, 4);
    if (p == 0) g_diag[i] = sigm(dacc + bias[0]);

    // V and U -> fp16
    {
        uint2 v0, v1;
        v0.x = packh2(acc[0], acc[1]); v0.y = packh2(acc[2], acc[3]);
        v1.x = packh2(acc[4], acc[5]); v1.y = packh2(acc[6], acc[7]);
        *(uint2*)&g_Vh[i * DIM + f0] = v0;
        *(uint2*)&g_Vh[i * DIM + f0 + 4] = v1;
        uint2 u0, u1;
        u0.x = packh2(u[f0], u[f0 + 1]);     u0.y = packh2(u[f0 + 2], u[f0 + 3]);
        u1.x = packh2(u[f0 + 4], u[f0 + 5]); u1.y = packh2(u[f0 + 6], u[f0 + 7]);
        *(uint2*)&g_Uh[i * DIM + f0] = u0;
        *(uint2*)&g_Uh[i * DIM + f0 + 4] = u1;
    }

    // gating + ES: batch b = p>>2, d-range [(p&3)*16, +16)
    const int b = p >> 2, dh = (p & 3) * 16;
    float gg = fmaxf(prof[b * NT + i] - THRESH, 0.0f);
    float go = __shfl_xor_sync(0xffffffffu, gg, 4);
    if (p == 0) g_flag[i] = (gg > 0.0f || go > 0.0f) ? 1 : 0;

#pragma unroll
    for (int d = dh; d < dh + 16; d += 4) {
        size_t src = (size_t)b * NT * DIM + i * DIM + d;
        float4 s4 = *(const float4*)&S[src];
        float4 e4 = make_float4(gg * s4.x, gg * s4.y, gg * s4.z, gg * s4.w);
        *(float4*)&g_ES[b][i * DIM + d] = e4;
        uint2 hv;
        hv.x = packh2(e4.x, e4.y);
        hv.y = packh2(e4.z, e4.w);
        *(uint2*)&g_Ef[(size_t)i * 128 + b * 64 + d] = hv;
    }
}

// ---------------------------------------------------------------------------
// Kernel B: deterministic compaction scan (Hillis-Steele) + g_done reset.
// ---------------------------------------------------------------------------
__global__ void scan_kernel() {
    __shared__ int sums[256];
    int t = threadIdx.x;
    if (t < 64) g_done[t] = 0;
    const int CH = NT / 256;  // 32
    int base = t * CH;
    int flags[CH];
    int s = 0;
#pragma unroll
    for (int k = 0; k < CH; k++) { flags[k] = g_flag[base + k]; s += flags[k]; }
    sums[t] = s;
    __syncthreads();
#pragma unroll
    for (int off = 1; off < 256; off <<= 1) {
        int v = (t >= off) ? sums[t - off] : 0;
        __syncthreads();
        sums[t] += v;
        __syncthreads();
    }
    if (t == 255) g_count = sums[255];
    int o = sums[t] - s;
#pragma unroll
    for (int k = 0; k < CH; k++)
        if (flags[k]) g_active[o++] = base + k;
}

// ---------------------------------------------------------------------------
// Main HMMA kernel. grid (64 j-tiles, SPLIT) x 256 threads (8 warps).
// 3-stage cp.async pipeline; prefetch gathers compacted rows via g_active.
// GEMM1 single-pass fp16; GEMM2 interleaved per-q.
// smem: U[128][72]h @0 (18432); stage s: V[128][72]h @18432+s*53248,
//       E[128][136]h @36864+s*53248. total 178176.
// ---------------------------------------------------------------------------
#define SM_V(s)  (18432 + (s) * 53248)
#define SM_E(s)  (36864 + (s) * 53248)
#define SMEM_MAIN 178176

__device__ __forceinline__ void prefetch_tile(uint32_t sb, int s, int i0, int t, int cnt) {
    uint32_t vh = sb + SM_V(s), eb = sb + SM_E(s);
#pragma unroll
    for (int it = 0; it < 4; it++) {
        int idx = it * 256 + t;
        int row = idx >> 3, ch = idx & 7;
        int gi = i0 + row;
        int ok = gi < cnt;
        int src = ok ? g_active[gi] : 0;
        int n = ok ? 16 : 0;
        CP16Z(vh + (uint32_t)(row * 144 + ch * 16),
              (const char*)&g_Vh[src * DIM + ch * 8], n);
    }
#pragma unroll
    for (int it = 0; it < 8; it++) {
        int idx = it * 256 + t;
        int row = idx >> 4, ch = idx & 15;
        int gi = i0 + row;
        int ok = gi < cnt;
        int src = ok ? g_active[gi] : 0;
        int n = ok ? 16 : 0;
        CP16Z(eb + (uint32_t)(row * 272 + ch * 16),
              (const char*)&g_Ef[(size_t)src * 128 + ch * 8], n);
    }
}

__global__ void __launch_bounds__(256, 1)
main_mma(const float* __restrict__ bias, const float* __restrict__ S,
         float* __restrict__ out) {
    extern __shared__ char sm[];
    const uint32_t sb = smem_u32(sm);
    const int t = threadIdx.x;
    const int w = t >> 5, lane = t & 31;
    const int gid = lane >> 2, tig = lane & 3;
    const int jt = blockIdx.x, part = blockIdx.y;
    const int j0 = jt * 128;
    const float bb = bias[0];

    __half* u_h = (__half*)sm;

    const int cnt = g_count;
    const int nT = (cnt + 127) >> 7;
    const int t0 = (part * nT) / SPLIT;
    const int t1 = ((part + 1) * nT) / SPLIT;
    const int Tl = t1 - t0;

    // stage U tile (persistent)
#pragma unroll
    for (int it = 0; it < 4; it++) {
        int idx = it * 256 + t;
        int row = idx >> 3, ch = idx & 7;
        *(uint4*)(u_h + row * 72 + ch * 8) = *(const uint4*)&g_Uh[(j0 + row) * DIM + ch * 8];
    }

    float acc2[16][4];
#pragma unroll
    for (int nt = 0; nt < 16; nt++)
#pragma unroll
        for (int q = 0; q < 4; q++) acc2[nt][q] = 0.0f;

    if (Tl > 0) { prefetch_tile(sb, 0, t0 * 128, t, cnt); CP_COMMIT(); }
    if (Tl > 1) { prefetch_tile(sb, 1, (t0 + 1) * 128, t, cnt); CP_COMMIT(); }
    __syncthreads();  // U visible

    // persistent A fragments of U for the 4 k-chunks
    uint32_t au[4][4];
    {
        const __half* ubase = u_h + (16 * w + gid) * 72 + 2 * tig;
#pragma unroll
        for (int kk = 0; kk < 4; kk++) {
            const __half* ph = ubase + 16 * kk;
            au[kk][0] = *(const uint32_t*)ph;
            au[kk][1] = *(const uint32_t*)(ph + 8 * 72);
            au[kk][2] = *(const uint32_t*)(ph + 8);
            au[kk][3] = *(const uint32_t*)(ph + 8 * 72 + 8);
        }
    }

    const uint32_t flb_v = (uint32_t)((lane & 15) * 144 + (lane >> 4) * 16);
    const uint32_t flb_e = (uint32_t)((lane & 15) * 272 + (lane >> 4) * 16);

    for (int lt = 0; lt < Tl; lt++) {
        const int s = lt % 3;
        if (lt + 2 < Tl) {
            prefetch_tile(sb, (lt + 2) % 3, (t0 + lt + 2) * 128, t, cnt);
            CP_COMMIT();
            CP_WAIT(2);
        } else if (lt + 1 < Tl) {
            CP_WAIT(1);
        } else {
            CP_WAIT(0);
        }
        __syncthreads();  // stage s data visible to all threads

        const uint32_t vhb = sb + SM_V(s) + flb_v;
        const uint32_t ebb = sb + SM_E(s) + flb_e;

        // q = 16-wide i-group: GEMM1 (score+sigmoid) then immediately GEMM2
#pragma unroll
        for (int q = 0; q < 8; q++) {
            float pa[2][4];
#pragma unroll
            for (int z = 0; z < 4; z++) { pa[0][z] = 0.0f; pa[1][z] = 0.0f; }
#pragma unroll
            for (int kk = 0; kk < 4; kk++) {
                uint32_t h0, h1, h2, h3;
                LDMX4(h0, h1, h2, h3, vhb + q * 2304 + kk * 32);
                MMA16816(pa[0], au[kk], h0, h2);
                MMA16816(pa[1], au[kk], h1, h3);
            }
            uint32_t ra[4];
            ra[0] = packh2(sigmf(pa[0][0] + bb), sigmf(pa[0][1] + bb));
            ra[1] = packh2(sigmf(pa[0][2] + bb), sigmf(pa[0][3] + bb));
            ra[2] = packh2(sigmf(pa[1][0] + bb), sigmf(pa[1][1] + bb));
            ra[3] = packh2(sigmf(pa[1][2] + bb), sigmf(pa[1][3] + bb));

            // GEMM2 contribution of this k16 chunk (i in [16q,16q+16))
#pragma unroll
            for (int ntp = 0; ntp < 8; ntp++) {
                uint32_t e0, e1, e2, e3;
                LDMX4T(e0, e1, e2, e3, ebb + q * 4352 + ntp * 32);
                MMA16816(acc2[2 * ntp], ra, e0, e1);
                MMA16816(acc2[2 * ntp + 1], ra, e2, e3);
            }
        }
        __syncthreads();  // all reads of stage s done before it is refilled
    }

    // write partial leaked
    {
        const int j = j0 + 16 * w + gid;
        float* dst0 = &g_part[part][(size_t)j * 128];
        float* dst1 = &g_part[part][(size_t)(j + 8) * 128];
#pragma unroll
        for (int nt = 0; nt < 16; nt++) {
            const int bd = 8 * nt + 2 * tig;
            *(float2*)(dst0 + bd) = make_float2(acc2[nt][0], acc2[nt][1]);
            *(float2*)(dst1 + bd) = make_float2(acc2[nt][2], acc2[nt][3]);
        }
    }

    // deterministic ticket: second CTA of this jt does the combine
    __threadfence();
    __syncthreads();
    volatile int* flag = (volatile int*)sm;
    if (t == 0) *(int*)sm = atomicAdd(&g_done[jt], 1);
    __syncthreads();
    if (*flag == 1) {
#pragma unroll
        for (int it = 0; it < 16; it++) {
            int idx = it * 256 + t;
            int j = idx >> 5;
            int c4 = idx & 31;
            int bd = c4 * 4;
            int b = bd >> 6, d = bd & 63;
            int jg = j0 + j;
            float4 a0 = *(const float4*)&g_part[0][(size_t)jg * 128 + bd];
            float4 a1 = *(const float4*)&g_part[1][(size_t)jg * 128 + bd];
            size_t oi = ((size_t)b * NT + jg) * DIM + d;
            float4 s4 = *(const float4*)&S[oi];
            float dj = g_diag[jg];
            float4 e4 = *(const float4*)&g_ES[b][jg * DIM + d];
            float4 o;
            o.x = s4.x + (a0.x + a1.x) - dj * e4.x;
            o.y = s4.y + (a0.y + a1.y) - dj * e4.y;
            o.z = s4.z + (a0.z + a1.z) - dj * e4.z;
            o.w = s4.w + (a0.w + a1.w) - dj * e4.w;
            *(float4*)&out[oi] = o;
        }
    }
}

// ---------------------------------------------------------------------------
extern "C" void kernel_launch(void* const* d_in, const int* in_sizes, int n_in,
                              void* d_out, int out_size) {
    const float* S    = (const float*)d_in[0];
    const float* prof = (const float*)d_in[1];
    const float* U    = (const float*)d_in[2];
    const float* W    = (const float*)d_in[3];
    const float* bias = (const float*)d_in[4];
    float* out = (float*)d_out;

    cudaFuncSetAttribute(main_mma, cudaFuncAttributeMaxDynamicSharedMemorySize, SMEM_MAIN);

    precompute_kernel<<<256, 256>>>(S, prof, U, W, bias);
    scan_kernel<<<1, 256>>>();
    main_mma<<<dim3(64, SPLIT), 256, SMEM_MAIN>>>(bias, S, out);
}

// round 12
// speedup vs baseline: 14.0861x; 1.0297x over previous
#include <cuda_runtime.h>
#include <cuda_fp16.h>
#include <cstdint>

#define NT 8192
#define DIM 64
#define THRESH 0.7f
#define SPLIT 2

// ---------------- global scratch (static, no allocation) ----------------
__device__ float g_diag[NT];
__device__ float g_ES[2][NT * DIM];                    // fp32 gated states (combine epilogue)
__device__ __half g_Uh[NT * DIM];                      // U fp16
__device__ __half g_Vh[NT * DIM];                      // V fp16 (uncompacted)
__device__ __half g_Ef[(size_t)NT * 128];              // ES fp16 rows: [i][bd], bd=b*64+d
__device__ float g_part[SPLIT][NT * 128];
__device__ int g_active[NT];
__device__ int g_count;
__device__ int g_flag[NT];
__device__ int g_done[64];

// ---------------- helpers ----------------
__device__ __forceinline__ uint32_t smem_u32(const void* p) {
    uint32_t a;
    asm("{ .reg .u64 t; cvta.to.shared.u64 t, %1; cvt.u32.u64 %0, t; }" : "=r"(a) : "l"(p));
    return a;
}
#define CP16Z(d, s, n) \
    asm volatile("cp.async.cg.shared.global [%0], [%1], 16, %2;" \
                 :: "r"(d), "l"(s), "r"(n) : "memory")
#define CP_COMMIT() asm volatile("cp.async.commit_group;" ::: "memory")
#define CP_WAIT(n) asm volatile("cp.async.wait_group %0;" :: "n"(n) : "memory")

#define MMA16816(c, a, b0, b1) \
    asm volatile("mma.sync.aligned.m16n8k16.row.col.f32.f16.f16.f32 " \
                 "{%0,%1,%2,%3}, {%4,%5,%6,%7}, {%8,%9}, {%0,%1,%2,%3};" \
                 : "+f"((c)[0]), "+f"((c)[1]), "+f"((c)[2]), "+f"((c)[3]) \
                 : "r"((a)[0]), "r"((a)[1]), "r"((a)[2]), "r"((a)[3]), \
                   "r"(b0), "r"(b1))

#define LDMX4(r0, r1, r2, r3, addr) \
    asm volatile("ldmatrix.sync.aligned.m8n8.x4.shared.b16 {%0,%1,%2,%3}, [%4];" \
                 : "=r"(r0), "=r"(r1), "=r"(r2), "=r"(r3) : "r"(addr))
#define LDMX4T(r0, r1, r2, r3, addr) \
    asm volatile("ldmatrix.sync.aligned.m8n8.x4.trans.shared.b16 {%0,%1,%2,%3}, [%4];" \
                 : "=r"(r0), "=r"(r1), "=r"(r2), "=r"(r3) : "r"(addr))

__device__ __forceinline__ float sigm(float x) { return 1.0f / (1.0f + __expf(-x)); }
__device__ __forceinline__ float sigmf(float x) {
    return __fdividef(1.0f, 1.0f + __expf(-x));
}
__device__ __forceinline__ uint32_t packh2(float x, float y) {
    __half2 h = __floats2half2_rn(x, y);
    return *(uint32_t*)&h;
}

// ---------------------------------------------------------------------------
// Kernel A: per-row precompute. grid 256 x 256 (8 threads/row, 32 rows/CTA).
// U rows staged in SMEM (no per-thread u[64] array -> no local-mem spill).
//   thread p=t&7: V cols [8p,8p+8), U fp16 d in [8p,8p+8),
//   ES batch p>>2, d-quarter (p&3)*16.
// ---------------------------------------------------------------------------
__global__ void precompute_kernel(const float* __restrict__ S,
                                  const float* __restrict__ prof,
                                  const float* __restrict__ U,
                                  const float* __restrict__ W,
                                  const float* __restrict__ bias) {
    __shared__ float Wsm[DIM * DIM];     // 16 KB
    __shared__ float Usm[32 * 72];       // 32 rows, pitch 72 floats (288B, 16B-mult)
    const int t = threadIdx.x;
    const int i0 = blockIdx.x * 32;

    for (int idx = t; idx < DIM * DIM / 4; idx += 256)
        *(float4*)&Wsm[idx * 4] = *(const float4*)&W[idx * 4];
#pragma unroll
    for (int it = 0; it < 2; it++) {
        int idx = it * 256 + t;          // 32 rows x 16 float4
        int row = idx >> 4, c4 = idx & 15;
        float4 v = *(const float4*)&U[(i0 + row) * DIM + c4 * 4];
        *(float4*)&Usm[row * 72 + c4 * 4] = v;
    }
    __syncthreads();

    const int p = t & 7;
    const int r = t >> 3;
    const int i = i0 + r;
    const float* u = &Usm[r * 72];

    // V columns [8p, 8p+8): smem u (broadcast) + float4 W loads
    const int f0 = p * 8;
    float acc[8];
#pragma unroll
    for (int c = 0; c < 8; c++) acc[c] = 0.0f;
    const float4* W4 = (const float4*)Wsm;
#pragma unroll 8
    for (int e = 0; e < DIM; e++) {
        float ue = u[e];
        float4 w0 = W4[e * 16 + p * 2];
        float4 w1 = W4[e * 16 + p * 2 + 1];
        acc[0] += ue * w0.x; acc[1] += ue * w0.y; acc[2] += ue * w0.z; acc[3] += ue * w0.w;
        acc[4] += ue * w1.x; acc[5] += ue * w1.y; acc[6] += ue * w1.z; acc[7] += ue * w1.w;
    }
    float dacc = 0.0f;
#pragma unroll
    for (int c = 0; c < 8; c++) dacc += acc[c] * u[f0 + c];
    dacc += __shfl_xor_sync(0xffffffffu, dacc, 1);
    dacc += __shfl_xor_sync(0xffffffffu, dacc, 2);
    dacc += __shfl_xor_sync(0xffffffffu, dacc, 4);
    if (p == 0) g_diag[i] = sigm(dacc + bias[0]);

    // V and U -> fp16
    {
        uint2 v0, v1;
        v0.x = packh2(acc[0], acc[1]); v0.y = packh2(acc[2], acc[3]);
        v1.x = packh2(acc[4], acc[5]); v1.y = packh2(acc[6], acc[7]);
        *(uint2*)&g_Vh[i * DIM + f0] = v0;
        *(uint2*)&g_Vh[i * DIM + f0 + 4] = v1;
        uint2 u0, u1;
        u0.x = packh2(u[f0], u[f0 + 1]);     u0.y = packh2(u[f0 + 2], u[f0 + 3]);
        u1.x = packh2(u[f0 + 4], u[f0 + 5]); u1.y = packh2(u[f0 + 6], u[f0 + 7]);
        *(uint2*)&g_Uh[i * DIM + f0] = u0;
        *(uint2*)&g_Uh[i * DIM + f0 + 4] = u1;
    }

    // gating + ES: batch b = p>>2, d-range [(p&3)*16, +16)
    const int b = p >> 2, dh = (p & 3) * 16;
    float gg = fmaxf(prof[b * NT + i] - THRESH, 0.0f);
    float go = __shfl_xor_sync(0xffffffffu, gg, 4);
    if (p == 0) g_flag[i] = (gg > 0.0f || go > 0.0f) ? 1 : 0;

#pragma unroll
    for (int d = dh; d < dh + 16; d += 4) {
        size_t src = (size_t)b * NT * DIM + i * DIM + d;
        float4 s4 = *(const float4*)&S[src];
        float4 e4 = make_float4(gg * s4.x, gg * s4.y, gg * s4.z, gg * s4.w);
        *(float4*)&g_ES[b][i * DIM + d] = e4;
        uint2 hv;
        hv.x = packh2(e4.x, e4.y);
        hv.y = packh2(e4.z, e4.w);
        *(uint2*)&g_Ef[(size_t)i * 128 + b * 64 + d] = hv;
    }
}

// ---------------------------------------------------------------------------
// Kernel B: deterministic compaction scan (Hillis-Steele) + g_done reset.
// ---------------------------------------------------------------------------
__global__ void scan_kernel() {
    __shared__ int sums[256];
    int t = threadIdx.x;
    if (t < 64) g_done[t] = 0;
    const int CH = NT / 256;  // 32
    int base = t * CH;
    int flags[CH];
    int s = 0;
#pragma unroll
    for (int k = 0; k < CH; k++) { flags[k] = g_flag[base + k]; s += flags[k]; }
    sums[t] = s;
    __syncthreads();
#pragma unroll
    for (int off = 1; off < 256; off <<= 1) {
        int v = (t >= off) ? sums[t - off] : 0;
        __syncthreads();
        sums[t] += v;
        __syncthreads();
    }
    if (t == 255) g_count = sums[255];
    int o = sums[t] - s;
#pragma unroll
    for (int k = 0; k < CH; k++)
        if (flags[k]) g_active[o++] = base + k;
}

// ---------------------------------------------------------------------------
// Main HMMA kernel. grid (64 j-tiles, SPLIT) x 256 threads (8 warps).
// 3-stage cp.async pipeline; prefetch gathers compacted rows via g_active.
// GEMM1 single-pass fp16; GEMM2 interleaved per-q.
// smem: U[128][72]h @0 (18432); stage s: V[128][72]h @18432+s*53248,
//       E[128][136]h @36864+s*53248. total 178176.
// ---------------------------------------------------------------------------
#define SM_V(s)  (18432 + (s) * 53248)
#define SM_E(s)  (36864 + (s) * 53248)
#define SMEM_MAIN 178176

__device__ __forceinline__ void prefetch_tile(uint32_t sb, int s, int i0, int t, int cnt) {
    uint32_t vh = sb + SM_V(s), eb = sb + SM_E(s);
#pragma unroll
    for (int it = 0; it < 4; it++) {
        int idx = it * 256 + t;
        int row = idx >> 3, ch = idx & 7;
        int gi = i0 + row;
        int ok = gi < cnt;
        int src = ok ? g_active[gi] : 0;
        int n = ok ? 16 : 0;
        CP16Z(vh + (uint32_t)(row * 144 + ch * 16),
              (const char*)&g_Vh[src * DIM + ch * 8], n);
    }
#pragma unroll
    for (int it = 0; it < 8; it++) {
        int idx = it * 256 + t;
        int row = idx >> 4, ch = idx & 15;
        int gi = i0 + row;
        int ok = gi < cnt;
        int src = ok ? g_active[gi] : 0;
        int n = ok ? 16 : 0;
        CP16Z(eb + (uint32_t)(row * 272 + ch * 16),
              (const char*)&g_Ef[(size_t)src * 128 + ch * 8], n);
    }
}

__global__ void __launch_bounds__(256, 1)
main_mma(const float* __restrict__ bias, const float* __restrict__ S,
         float* __restrict__ out) {
    extern __shared__ char sm[];
    const uint32_t sb = smem_u32(sm);
    const int t = threadIdx.x;
    const int w = t >> 5, lane = t & 31;
    const int gid = lane >> 2, tig = lane & 3;
    const int jt = blockIdx.x, part = blockIdx.y;
    const int j0 = jt * 128;
    const float bb = bias[0];

    __half* u_h = (__half*)sm;

    const int cnt = g_count;
    const int nT = (cnt + 127) >> 7;
    const int t0 = (part * nT) / SPLIT;
    const int t1 = ((part + 1) * nT) / SPLIT;
    const int Tl = t1 - t0;

    // stage U tile (persistent)
#pragma unroll
    for (int it = 0; it < 4; it++) {
        int idx = it * 256 + t;
        int row = idx >> 3, ch = idx & 7;
        *(uint4*)(u_h + row * 72 + ch * 8) = *(const uint4*)&g_Uh[(j0 + row) * DIM + ch * 8];
    }

    float acc2[16][4];
#pragma unroll
    for (int nt = 0; nt < 16; nt++)
#pragma unroll
        for (int q = 0; q < 4; q++) acc2[nt][q] = 0.0f;

    if (Tl > 0) { prefetch_tile(sb, 0, t0 * 128, t, cnt); CP_COMMIT(); }
    if (Tl > 1) { prefetch_tile(sb, 1, (t0 + 1) * 128, t, cnt); CP_COMMIT(); }
    __syncthreads();  // U visible

    // persistent A fragments of U for the 4 k-chunks
    uint32_t au[4][4];
    {
        const __half* ubase = u_h + (16 * w + gid) * 72 + 2 * tig;
#pragma unroll
        for (int kk = 0; kk < 4; kk++) {
            const __half* ph = ubase + 16 * kk;
            au[kk][0] = *(const uint32_t*)ph;
            au[kk][1] = *(const uint32_t*)(ph + 8 * 72);
            au[kk][2] = *(const uint32_t*)(ph + 8);
            au[kk][3] = *(const uint32_t*)(ph + 8 * 72 + 8);
        }
    }

    const uint32_t flb_v = (uint32_t)((lane & 15) * 144 + (lane >> 4) * 16);
    const uint32_t flb_e = (uint32_t)((lane & 15) * 272 + (lane >> 4) * 16);

    for (int lt = 0; lt < Tl; lt++) {
        const int s = lt % 3;
        if (lt + 2 < Tl) {
            prefetch_tile(sb, (lt + 2) % 3, (t0 + lt + 2) * 128, t, cnt);
            CP_COMMIT();
            CP_WAIT(2);
        } else if (lt + 1 < Tl) {
            CP_WAIT(1);
        } else {
            CP_WAIT(0);
        }
        __syncthreads();  // stage s data visible to all threads

        const uint32_t vhb = sb + SM_V(s) + flb_v;
        const uint32_t ebb = sb + SM_E(s) + flb_e;

        // q = 16-wide i-group: GEMM1 (score+sigmoid) then immediately GEMM2
#pragma unroll
        for (int q = 0; q < 8; q++) {
            float pa[2][4];
#pragma unroll
            for (int z = 0; z < 4; z++) { pa[0][z] = 0.0f; pa[1][z] = 0.0f; }
#pragma unroll
            for (int kk = 0; kk < 4; kk++) {
                uint32_t h0, h1, h2, h3;
                LDMX4(h0, h1, h2, h3, vhb + q * 2304 + kk * 32);
                MMA16816(pa[0], au[kk], h0, h2);
                MMA16816(pa[1], au[kk], h1, h3);
            }
            uint32_t ra[4];
            ra[0] = packh2(sigmf(pa[0][0] + bb), sigmf(pa[0][1] + bb));
            ra[1] = packh2(sigmf(pa[0][2] + bb), sigmf(pa[0][3] + bb));
            ra[2] = packh2(sigmf(pa[1][0] + bb), sigmf(pa[1][1] + bb));
            ra[3] = packh2(sigmf(pa[1][2] + bb), sigmf(pa[1][3] + bb));

            // GEMM2 contribution of this k16 chunk (i in [16q,16q+16))
#pragma unroll
            for (int ntp = 0; ntp < 8; ntp++) {
                uint32_t e0, e1, e2, e3;
                LDMX4T(e0, e1, e2, e3, ebb + q * 4352 + ntp * 32);
                MMA16816(acc2[2 * ntp], ra, e0, e1);
                MMA16816(acc2[2 * ntp + 1], ra, e2, e3);
            }
        }
        __syncthreads();  // all reads of stage s done before it is refilled
    }

    // write partial leaked
    {
        const int j = j0 + 16 * w + gid;
        float* dst0 = &g_part[part][(size_t)j * 128];
        float* dst1 = &g_part[part][(size_t)(j + 8) * 128];
#pragma unroll
        for (int nt = 0; nt < 16; nt++) {
            const int bd = 8 * nt + 2 * tig;
            *(float2*)(dst0 + bd) = make_float2(acc2[nt][0], acc2[nt][1]);
            *(float2*)(dst1 + bd) = make_float2(acc2[nt][2], acc2[nt][3]);
        }
    }

    // deterministic ticket: second CTA of this jt does the combine
    __threadfence();
    __syncthreads();
    volatile int* flag = (volatile int*)sm;
    if (t == 0) *(int*)sm = atomicAdd(&g_done[jt], 1);
    __syncthreads();
    if (*flag == 1) {
#pragma unroll
        for (int it = 0; it < 16; it++) {
            int idx = it * 256 + t;
            int j = idx >> 5;
            int c4 = idx & 31;
            int bd = c4 * 4;
            int b = bd >> 6, d = bd & 63;
            int jg = j0 + j;
            float4 a0 = *(const float4*)&g_part[0][(size_t)jg * 128 + bd];
            float4 a1 = *(const float4*)&g_part[1][(size_t)jg * 128 + bd];
            size_t oi = ((size_t)b * NT + jg) * DIM + d;
            float4 s4 = *(const float4*)&S[oi];
            float dj = g_diag[jg];
            float4 e4 = *(const float4*)&g_ES[b][jg * DIM + d];
            float4 o;
            o.x = s4.x + (a0.x + a1.x) - dj * e4.x;
            o.y = s4.y + (a0.y + a1.y) - dj * e4.y;
            o.z = s4.z + (a0.z + a1.z) - dj * e4.z;
            o.w = s4.w + (a0.w + a1.w) - dj * e4.w;
            *(float4*)&out[oi] = o;
        }
    }
}

// ---------------------------------------------------------------------------
extern "C" void kernel_launch(void* const* d_in, const int* in_sizes, int n_in,
                              void* d_out, int out_size) {
    const float* S    = (const float*)d_in[0];
    const float* prof = (const float*)d_in[1];
    const float* U    = (const float*)d_in[2];
    const float* W    = (const float*)d_in[3];
    const float* bias = (const float*)d_in[4];
    float* out = (float*)d_out;

    cudaFuncSetAttribute(main_mma, cudaFuncAttributeMaxDynamicSharedMemorySize, SMEM_MAIN);

    precompute_kernel<<<256, 256>>>(S, prof, U, W, bias);
    scan_kernel<<<1, 256>>>();
    main_mma<<<dim3(64, SPLIT), 256, SMEM_MAIN>>>(bias, S, out);
}